// round 8
// baseline (speedup 1.0000x reference)
#include <cuda_runtime.h>
#include <cuda_bf16.h>
#include <cstdint>
#include <math.h>

#define HID   2048
#define HID3  6144
#define NH    16
#define HD    128
#define BATCH 4
#define SEQ   2048
#define MROWS 8192
#define K2    4096          // storage: [hi | lo] bf16 per row
#define BKG   64            // bf16 k-chunk per stage (128B rows)
#define NCHT  96            // 3-term split: Ah*Bh + Al*Bh + Ah*Bl
// GEMM tile: 256x128, 8 warps x (64x64), 2 stages
#define GBM   256
#define GBN   128
#define GSTG_BYTES 49152    // 32KB A + 16KB B
#define GEMM_SMEM  (2*GSTG_BYTES)   // 98304

// ---------------- scratch (no allocations allowed) ----------------
__device__ __nv_bfloat16 g_xc[(size_t)MROWS * K2];
__device__ __nv_bfloat16 g_wqkvc[(size_t)HID3 * K2];
__device__ __nv_bfloat16 g_wdc[(size_t)HID * K2];
__device__ __nv_bfloat16 g_attnc[(size_t)MROWS * K2];
// attention operands: [bh][s][256] for Q,K ; [bh][256][s] for V^T (hi rows 0-127, lo 128-255)
__device__ __nv_bfloat16 g_qs[(size_t)BATCH * NH * SEQ * 256];
__device__ __nv_bfloat16 g_ks[(size_t)BATCH * NH * SEQ * 256];
__device__ __nv_bfloat16 g_vt[(size_t)BATCH * NH * 256 * SEQ];

// ---------------- helpers ----------------
__device__ __forceinline__ uint32_t s2u(const void* p) {
    uint32_t a;
    asm("{ .reg .u64 t; cvta.to.shared.u64 t, %1; cvt.u32.u64 %0, t; }"
        : "=r"(a) : "l"(p));
    return a;
}
__device__ __forceinline__ void cp16(uint32_t dst, const void* src) {
    asm volatile("cp.async.cg.shared.global [%0], [%1], 16;"
                 :: "r"(dst), "l"(src));
}
__device__ __forceinline__ void ldsm4(uint32_t* r, uint32_t addr) {
    asm volatile("ldmatrix.sync.aligned.m8n8.x4.shared.b16 {%0,%1,%2,%3}, [%4];"
        : "=r"(r[0]), "=r"(r[1]), "=r"(r[2]), "=r"(r[3]) : "r"(addr));
}
__device__ __forceinline__ void mma16816(float* c, const uint32_t* a,
                                         uint32_t b0, uint32_t b1) {
    asm volatile("mma.sync.aligned.m16n8k16.row.col.f32.bf16.bf16.f32 "
        "{%0,%1,%2,%3}, {%4,%5,%6,%7}, {%8,%9}, {%0,%1,%2,%3};"
        : "+f"(c[0]), "+f"(c[1]), "+f"(c[2]), "+f"(c[3])
        : "r"(a[0]), "r"(a[1]), "r"(a[2]), "r"(a[3]), "r"(b0), "r"(b1));
}
__device__ __forceinline__ uint32_t pkbf(float lo, float hi) {
    uint32_t r;
    asm("cvt.rn.bf16x2.f32 %0, %1, %2;" : "=r"(r) : "f"(hi), "f"(lo));
    return r;
}
__device__ __forceinline__ void split1(float v, unsigned short& h, unsigned short& l) {
    __nv_bfloat16 hb = __float2bfloat16(v);
    __nv_bfloat16 lb = __float2bfloat16(v - __bfloat162float(hb));
    h = __bfloat16_as_ushort(hb);
    l = __bfloat16_as_ushort(lb);
}

// ---------------- split conversion: fp32[rows][2048] -> bf16[rows][hi|lo] ------
__global__ __launch_bounds__(256) void split_kernel(const float* __restrict__ in,
                                                    __nv_bfloat16* __restrict__ out,
                                                    int rows)
{
    size_t i = (size_t)blockIdx.x * 256 + threadIdx.x;
    size_t n4 = (size_t)rows * HID / 4;
    if (i >= n4) return;
    size_t e = i * 4;
    size_t r = e >> 11;
    int    c = (int)(e & 2047);
    float4 v = ((const float4*)in)[i];
    unsigned short h0,h1,h2,h3,l0,l1,l2,l3;
    split1(v.x,h0,l0); split1(v.y,h1,l1); split1(v.z,h2,l2); split1(v.w,h3,l3);
    __nv_bfloat16* o = out + r * K2;
    *(ushort4*)(o + c)       = make_ushort4(h0,h1,h2,h3);
    *(ushort4*)(o + HID + c) = make_ushort4(l0,l1,l2,l3);
}

// ============= shared GEMM mainloop macro-body (256x128 tile, 64x64/warp) ======
// defines: acc[4][8][4] accumulators after the loop
#define GEMM_MAINLOOP(A_, B_)                                                    \
    const uint32_t sb = s2u(sm);                                                 \
    const int tid = threadIdx.x;                                                 \
    const int wid = tid >> 5, lane = tid & 31;                                   \
    const int wm = wid & 3, wn = wid >> 2;                                       \
    const int lm_row = lane & 15;                                                \
    const int lm_hi  = (lane >> 4) << 4;                                         \
    auto issue = [&](int ch) {                                                   \
        int ach = (ch < 64) ? ch : (ch - 64);                                    \
        int bch = (ch < 32) ? ch : (ch - 32);                                    \
        uint32_t st = sb + (ch & 1) * GSTG_BYTES;                                \
        const __nv_bfloat16* Ab = (A_) + (size_t)ach * BKG;                      \
        const __nv_bfloat16* Bb = (B_) + (size_t)bch * BKG;                      \
        _Pragma("unroll")                                                        \
        for (int i = 0; i < 8; i++) {                                            \
            int u = i * 256 + tid;                                               \
            int r = u >> 3, c = u & 7;                                           \
            uint32_t sw = (uint32_t)(r * 128) + (uint32_t)((c * 16) ^ ((r & 7) << 4)); \
            cp16(st + sw, Ab + (bm + r) * K2 + c * 8);                           \
        }                                                                        \
        _Pragma("unroll")                                                        \
        for (int i = 0; i < 4; i++) {                                            \
            int u = i * 256 + tid;                                               \
            int r = u >> 3, c = u & 7;                                           \
            uint32_t sw = (uint32_t)(r * 128) + (uint32_t)((c * 16) ^ ((r & 7) << 4)); \
            cp16(st + 32768 + sw, Bb + (bn + r) * K2 + c * 8);                   \
        }                                                                        \
        asm volatile("cp.async.commit_group;");                                  \
    };                                                                           \
    issue(0);                                                                    \
    issue(1);                                                                    \
    float acc[4][8][4];                                                          \
    _Pragma("unroll")                                                            \
    for (int mi = 0; mi < 4; mi++)                                               \
        _Pragma("unroll")                                                        \
        for (int ni = 0; ni < 8; ni++)                                           \
            _Pragma("unroll")                                                    \
            for (int q = 0; q < 4; q++) acc[mi][ni][q] = 0.f;                    \
    for (int ch = 0; ch < NCHT; ch++) {                                          \
        if (ch + 1 < NCHT) asm volatile("cp.async.wait_group 1;");               \
        else               asm volatile("cp.async.wait_group 0;");               \
        __syncthreads();                                                         \
        uint32_t st = sb + (ch & 1) * GSTG_BYTES;                                \
        _Pragma("unroll")                                                        \
        for (int kk = 0; kk < 64; kk += 16) {                                    \
            uint32_t a[4][4];                                                    \
            _Pragma("unroll")                                                    \
            for (int mi = 0; mi < 4; mi++) {                                     \
                int row = wm * 64 + mi * 16 + lm_row;                            \
                uint32_t byte = (uint32_t)(kk * 2 + lm_hi);                      \
                ldsm4(a[mi], st + row * 128 + (byte ^ ((row & 7) << 4)));        \
            }                                                                    \
            uint32_t b[4][4];                                                    \
            _Pragma("unroll")                                                    \
            for (int g = 0; g < 4; g++) {                                        \
                int row = wn * 64 + g * 16 + lm_row;                             \
                uint32_t byte = (uint32_t)(kk * 2 + lm_hi);                      \
                ldsm4(b[g], st + 32768 + row * 128 + (byte ^ ((row & 7) << 4))); \
            }                                                                    \
            _Pragma("unroll")                                                    \
            for (int mi = 0; mi < 4; mi++)                                       \
                _Pragma("unroll")                                                \
                for (int ni = 0; ni < 8; ni++)                                   \
                    mma16816(acc[mi][ni], a[mi], b[ni >> 1][ni & 1],             \
                             b[ni >> 1][(ni & 1) + 2]);                          \
        }                                                                        \
        __syncthreads();                                                         \
        if (ch + 2 < NCHT) issue(ch + 2);                                        \
    }

// ---------------- QKV GEMM with fused operand epilogue ----------------
__global__ __launch_bounds__(256, 1) void gemm_qkv_kernel(
    const __nv_bfloat16* __restrict__ A, const __nv_bfloat16* __restrict__ B,
    const float* __restrict__ bias)
{
    extern __shared__ char sm[];
    const size_t bm = (size_t)blockIdx.y * GBM;
    const size_t bn = (size_t)blockIdx.x * GBN;

    GEMM_MAINLOOP(A, B)

    // ---- fused epilogue ----
    const int r0 = wm * 64 + (lane >> 2);          // + mi*16 (+8)
    const int c0 = wn * 64 + (lane & 3) * 2;       // + ni*8
    const int sec = (int)(bn >> 11);               // 0=Q 1=K 2=V
    const int hh  = ((int)bn & 2047) >> 7;
    const int b_  = (int)(bm >> 11);
    const int s_base = (int)bm & 2047;             // 256-aligned, fits in batch
    const size_t bh = (size_t)b_ * NH + hh;
    const float qscale = 0.08838834764831845f;

    if (sec < 2) {
        __nv_bfloat16* dst = (sec == 0) ? g_qs : g_ks;
        const float sc = (sec == 0) ? qscale : 1.f;
#pragma unroll
        for (int mi = 0; mi < 4; mi++)
#pragma unroll
            for (int ni = 0; ni < 8; ni++) {
                int d = c0 + ni * 8;
                float2 bv = *(const float2*)(bias + bn + d);
                float o0 = (acc[mi][ni][0] + bv.x) * sc;
                float o1 = (acc[mi][ni][1] + bv.y) * sc;
                float o2 = (acc[mi][ni][2] + bv.x) * sc;
                float o3 = (acc[mi][ni][3] + bv.y) * sc;
                unsigned short h0,h1,h2,h3,l0,l1,l2,l3;
                split1(o0,h0,l0); split1(o1,h1,l1);
                split1(o2,h2,l2); split1(o3,h3,l3);
                int ra = s_base + r0 + mi * 16;
                __nv_bfloat16* pa = dst + (bh * SEQ + ra) * 256 + d;
                *(ushort2*)pa         = make_ushort2(h0,h1);
                *(ushort2*)(pa + 128) = make_ushort2(l0,l1);
                __nv_bfloat16* pb = pa + 8 * 256;
                *(ushort2*)pb         = make_ushort2(h2,h3);
                *(ushort2*)(pb + 128) = make_ushort2(l2,l3);
            }
    } else {
        // V: transpose through smem in two 128-row halves -> g_vt
        float* smT = (float*)sm;                   // [128 d][129]
#pragma unroll
        for (int half = 0; half < 2; half++) {
            __syncthreads();
            if ((wm >> 1) == half) {
#pragma unroll
                for (int mi = 0; mi < 4; mi++)
#pragma unroll
                    for (int ni = 0; ni < 8; ni++) {
                        int d = c0 + ni * 8;
                        float2 bv = *(const float2*)(bias + bn + d);
                        int ra = (wm & 1) * 64 + mi * 16 + (lane >> 2);
                        smT[d * 129 + ra]           = acc[mi][ni][0] + bv.x;
                        smT[(d + 1) * 129 + ra]     = acc[mi][ni][1] + bv.y;
                        smT[d * 129 + ra + 8]       = acc[mi][ni][2] + bv.x;
                        smT[(d + 1) * 129 + ra + 8] = acc[mi][ni][3] + bv.y;
                    }
            }
            __syncthreads();
            const int d = tid >> 1;
            const int sOff = (tid & 1) * 64;
            const int sg = s_base + half * 128 + sOff;
            __nv_bfloat16* ph = g_vt + (bh * 256 + d) * SEQ + sg;
            __nv_bfloat16* pl = ph + (size_t)128 * SEQ;
#pragma unroll
            for (int i = 0; i < 16; i++) {
                int s = i * 4;
                float v0 = smT[d * 129 + sOff + s + 0];
                float v1 = smT[d * 129 + sOff + s + 1];
                float v2 = smT[d * 129 + sOff + s + 2];
                float v3 = smT[d * 129 + sOff + s + 3];
                unsigned short h0,h1,h2,h3,l0,l1,l2,l3;
                split1(v0,h0,l0); split1(v1,h1,l1);
                split1(v2,h2,l2); split1(v3,h3,l3);
                *(ushort4*)(ph + s) = make_ushort4(h0,h1,h2,h3);
                *(ushort4*)(pl + s) = make_ushort4(l0,l1,l2,l3);
            }
        }
    }
}

// ---------------- dense GEMM (fp32 out) ----------------
__global__ __launch_bounds__(256, 1) void gemm_dense_kernel(
    const __nv_bfloat16* __restrict__ A, const __nv_bfloat16* __restrict__ B,
    const float* __restrict__ bias, float* __restrict__ C, int Ncols)
{
    extern __shared__ char sm[];
    const size_t bm = (size_t)blockIdx.y * GBM;
    const size_t bn = (size_t)blockIdx.x * GBN;

    GEMM_MAINLOOP(A, B)

    const int r0 = wm * 64 + (lane >> 2);
    const int c0 = wn * 64 + (lane & 3) * 2;
#pragma unroll
    for (int mi = 0; mi < 4; mi++)
#pragma unroll
        for (int ni = 0; ni < 8; ni++) {
            size_t col = bn + c0 + ni * 8;
            float2 bv = *(const float2*)(bias + col);
            float* p0 = C + (bm + r0 + mi * 16) * (size_t)Ncols + col;
            float* p1 = p0 + 8 * (size_t)Ncols;
            *(float2*)p0 = make_float2(acc[mi][ni][0] + bv.x, acc[mi][ni][1] + bv.y);
            *(float2*)p1 = make_float2(acc[mi][ni][2] + bv.x, acc[mi][ni][3] + bv.y);
        }
}

// ---------------- HMMA causal flash attention (unchanged) ----------------
#define ATTN_SMEM 196608
__global__ __launch_bounds__(256, 1) void attn_hmma_kernel()
{
    extern __shared__ char smc[];
    const uint32_t sb = s2u(smc);
    const int tid = threadIdx.x, w = tid >> 5, lane = tid & 31;
    const int qb = 15 - blockIdx.x, h = blockIdx.y, b = blockIdx.z;
    const int bh = b * NH + h;
    const int nkb = (qb + 1) * 2;
    const int lm_row = lane & 15;
    const int lm_hi  = (lane >> 4) << 4;

    {
        const __nv_bfloat16* Qg = g_qs + ((size_t)bh * SEQ + qb * 128) * 256;
#pragma unroll
        for (int i = 0; i < 16; i++) {
            int u = i * 256 + tid;
            int r = u >> 5, c = u & 31;
            cp16(sb + r * 512 + ((c * 16) ^ ((r & 7) << 4)), Qg + (size_t)r * 256 + c * 8);
        }
    }
    auto issue_kv = [&](int kb) {
        uint32_t kst = sb + 65536 + (kb & 1) * 65536;
#pragma unroll
        for (int i = 0; i < 8; i++) {
            int u = i * 256 + tid;
            int r = u >> 5, c = u & 31;
            cp16(kst + r * 512 + ((c * 16) ^ ((r & 7) << 4)),
                 g_ks + ((size_t)bh * SEQ + kb * 64 + r) * 256 + c * 8);
        }
#pragma unroll
        for (int i = 0; i < 8; i++) {
            int u = i * 256 + tid;
            int r = u >> 3, c = u & 7;
            cp16(kst + 32768 + r * 128 + ((c * 16) ^ ((r & 7) << 4)),
                 g_vt + ((size_t)bh * 256 + r) * SEQ + kb * 64 + c * 8);
        }
        asm volatile("cp.async.commit_group;");
    };
    issue_kv(0);
    if (nkb > 1) issue_kv(1);

    float oacc[16][4];
#pragma unroll
    for (int g = 0; g < 16; g++)
#pragma unroll
        for (int e = 0; e < 4; e++) oacc[g][e] = 0.f;
    float m0 = -1e30f, m1 = -1e30f, lp0 = 0.f, lp1 = 0.f;

    const int row0 = qb * 128 + w * 16 + (lane >> 2);
    const int wrow_max = qb * 128 + w * 16 + 15;

    for (int kb = 0; kb < nkb; kb++) {
        if (kb + 1 < nkb) asm volatile("cp.async.wait_group 1;");
        else              asm volatile("cp.async.wait_group 0;");
        __syncthreads();

        const bool active = (kb * 64) <= wrow_max;
        if (active) {
            const uint32_t kst = sb + 65536 + (kb & 1) * 65536;
            const uint32_t vst = kst + 32768;

            float sacc[8][4];
#pragma unroll
            for (int j = 0; j < 8; j++)
#pragma unroll
                for (int e = 0; e < 4; e++) sacc[j][e] = 0.f;

#pragma unroll
            for (int kk = 0; kk < 8; kk++) {
                const int qrow = w * 16 + lm_row;
                uint32_t qa = sb + qrow * 512 +
                              ((uint32_t)(kk * 32 + lm_hi) ^ ((qrow & 7) << 4));
                uint32_t ah[4], al[4];
                ldsm4(ah, qa);
                ldsm4(al, qa + 256);
#pragma unroll
                for (int g = 0; g < 4; g++) {
                    const int krow = g * 16 + lm_row;
                    uint32_t ka = kst + krow * 512 +
                                  ((uint32_t)(kk * 32 + lm_hi) ^ ((krow & 7) << 4));
                    uint32_t bhh[4], bll[4];
                    ldsm4(bhh, ka);
                    ldsm4(bll, ka + 256);
                    mma16816(sacc[2*g],   ah, bhh[0], bhh[2]);
                    mma16816(sacc[2*g+1], ah, bhh[1], bhh[3]);
                    mma16816(sacc[2*g],   al, bhh[0], bhh[2]);
                    mma16816(sacc[2*g+1], al, bhh[1], bhh[3]);
                    mma16816(sacc[2*g],   ah, bll[0], bll[2]);
                    mma16816(sacc[2*g+1], ah, bll[1], bll[3]);
                }
            }

            float mx0 = -1e30f, mx1 = -1e30f;
#pragma unroll
            for (int j = 0; j < 8; j++) {
                int colb = kb * 64 + j * 8 + (lane & 3) * 2;
                if (colb     > row0)     sacc[j][0] = -1e30f;
                if (colb + 1 > row0)     sacc[j][1] = -1e30f;
                if (colb     > row0 + 8) sacc[j][2] = -1e30f;
                if (colb + 1 > row0 + 8) sacc[j][3] = -1e30f;
                mx0 = fmaxf(mx0, fmaxf(sacc[j][0], sacc[j][1]));
                mx1 = fmaxf(mx1, fmaxf(sacc[j][2], sacc[j][3]));
            }
            mx0 = fmaxf(mx0, __shfl_xor_sync(0xffffffffu, mx0, 1));
            mx0 = fmaxf(mx0, __shfl_xor_sync(0xffffffffu, mx0, 2));
            mx1 = fmaxf(mx1, __shfl_xor_sync(0xffffffffu, mx1, 1));
            mx1 = fmaxf(mx1, __shfl_xor_sync(0xffffffffu, mx1, 2));
            float mn0 = fmaxf(m0, mx0), mn1 = fmaxf(m1, mx1);
            float al0 = __expf(m0 - mn0), al1 = __expf(m1 - mn1);
            m0 = mn0; m1 = mn1;
            float s0 = 0.f, s1 = 0.f;
#pragma unroll
            for (int j = 0; j < 8; j++) {
                sacc[j][0] = __expf(sacc[j][0] - mn0); s0 += sacc[j][0];
                sacc[j][1] = __expf(sacc[j][1] - mn0); s0 += sacc[j][1];
                sacc[j][2] = __expf(sacc[j][2] - mn1); s1 += sacc[j][2];
                sacc[j][3] = __expf(sacc[j][3] - mn1); s1 += sacc[j][3];
            }
            lp0 = lp0 * al0 + s0;
            lp1 = lp1 * al1 + s1;
#pragma unroll
            for (int g = 0; g < 16; g++) {
                oacc[g][0] *= al0; oacc[g][1] *= al0;
                oacc[g][2] *= al1; oacc[g][3] *= al1;
            }

#pragma unroll
            for (int t = 0; t < 4; t++) {
                const int f0 = 2 * t, f1 = 2 * t + 1;
                float ph[8], pl[8];
#pragma unroll
                for (int e = 0; e < 4; e++) {
                    float p0v = sacc[f0][e], p1v = sacc[f1][e];
                    float h0f = __bfloat162float(__float2bfloat16(p0v));
                    float h1f = __bfloat162float(__float2bfloat16(p1v));
                    ph[e]     = h0f; pl[e]     = p0v - h0f;
                    ph[4 + e] = h1f; pl[4 + e] = p1v - h1f;
                }
                uint32_t aPh[4], aPl[4];
                aPh[0] = pkbf(ph[0], ph[1]); aPh[1] = pkbf(ph[2], ph[3]);
                aPh[2] = pkbf(ph[4], ph[5]); aPh[3] = pkbf(ph[6], ph[7]);
                aPl[0] = pkbf(pl[0], pl[1]); aPl[1] = pkbf(pl[2], pl[3]);
                aPl[2] = pkbf(pl[4], pl[5]); aPl[3] = pkbf(pl[6], pl[7]);
#pragma unroll
                for (int g = 0; g < 8; g++) {
                    const int vrow = g * 16 + lm_row;
                    uint32_t va = vst + vrow * 128 +
                                  ((uint32_t)(t * 32 + lm_hi) ^ ((vrow & 7) << 4));
                    uint32_t bhh[4], bll[4];
                    ldsm4(bhh, va);
                    ldsm4(bll, va + 16384);
                    mma16816(oacc[2*g],   aPh, bhh[0], bhh[2]);
                    mma16816(oacc[2*g+1], aPh, bhh[1], bhh[3]);
                    mma16816(oacc[2*g],   aPl, bhh[0], bhh[2]);
                    mma16816(oacc[2*g+1], aPl, bhh[1], bhh[3]);
                    mma16816(oacc[2*g],   aPh, bll[0], bll[2]);
                    mma16816(oacc[2*g+1], aPh, bll[1], bll[3]);
                }
            }
        }
        __syncthreads();
        if (kb + 2 < nkb) issue_kv(kb + 2);
    }

    lp0 += __shfl_xor_sync(0xffffffffu, lp0, 1);
    lp0 += __shfl_xor_sync(0xffffffffu, lp0, 2);
    lp1 += __shfl_xor_sync(0xffffffffu, lp1, 1);
    lp1 += __shfl_xor_sync(0xffffffffu, lp1, 2);
    const float inv0 = 1.f / lp0, inv1 = 1.f / lp1;

    const size_t row = (size_t)b * SEQ + qb * 128 + w * 16 + (lane >> 2);
    const int colb = h * 128 + (lane & 3) * 2;
#pragma unroll
    for (int g = 0; g < 16; g++) {
        int col = colb + g * 8;
        float v0 = oacc[g][0] * inv0, v1 = oacc[g][1] * inv0;
        float v2 = oacc[g][2] * inv1, v3 = oacc[g][3] * inv1;
        unsigned short h0,h1,h2,h3,l0,l1,l2,l3;
        split1(v0,h0,l0); split1(v1,h1,l1);
        split1(v2,h2,l2); split1(v3,h3,l3);
        __nv_bfloat16* pa = g_attnc + row * K2 + col;
        *(ushort2*)pa          = make_ushort2(h0,h1);
        *(ushort2*)(pa + HID)  = make_ushort2(l0,l1);
        __nv_bfloat16* pb = pa + 8 * K2;
        *(ushort2*)pb          = make_ushort2(h2,h3);
        *(ushort2*)(pb + HID)  = make_ushort2(l2,l3);
    }
}

// ---------------- launch ----------------
extern "C" void kernel_launch(void* const* d_in, const int* in_sizes, int n_in,
                              void* d_out, int out_size)
{
    (void)in_sizes; (void)n_in; (void)out_size;
    const float* x       = (const float*)d_in[0];
    const float* w_qkv   = (const float*)d_in[1];
    const float* b_qkv   = (const float*)d_in[2];
    const float* w_dense = (const float*)d_in[3];
    const float* b_dense = (const float*)d_in[4];
    float* out = (float*)d_out;

    __nv_bfloat16 *xc, *wqkvc, *wdc, *attnc;
    cudaGetSymbolAddress((void**)&xc, g_xc);
    cudaGetSymbolAddress((void**)&wqkvc, g_wqkvc);
    cudaGetSymbolAddress((void**)&wdc, g_wdc);
    cudaGetSymbolAddress((void**)&attnc, g_attnc);

    cudaFuncSetAttribute(gemm_qkv_kernel,
                         cudaFuncAttributeMaxDynamicSharedMemorySize, GEMM_SMEM);
    cudaFuncSetAttribute(gemm_dense_kernel,
                         cudaFuncAttributeMaxDynamicSharedMemorySize, GEMM_SMEM);
    cudaFuncSetAttribute(attn_hmma_kernel,
                         cudaFuncAttributeMaxDynamicSharedMemorySize, ATTN_SMEM);

    // split conversions (fp32 -> bf16 hi|lo)
    split_kernel<<<(MROWS * HID / 4 + 255) / 256, 256>>>(x, xc, MROWS);
    split_kernel<<<(HID3 * HID / 4 + 255) / 256, 256>>>(w_qkv, wqkvc, HID3);
    split_kernel<<<(HID  * HID / 4 + 255) / 256, 256>>>(w_dense, wdc, HID);

    // 1) QKV GEMM with fused operand-prep epilogue (256x128 tiles)
    gemm_qkv_kernel<<<dim3(HID3 / GBN, MROWS / GBM), 256, GEMM_SMEM>>>(
        xc, wqkvc, b_qkv);

    // 2) HMMA flash attention (writes bf16 split directly)
    attn_hmma_kernel<<<dim3(16, NH, BATCH), 256, ATTN_SMEM>>>();

    // 3) out = attn @ Wdense^T + b (256x128 tiles)
    gemm_dense_kernel<<<dim3(HID / GBN, MROWS / GBM), 256, GEMM_SMEM>>>(
        attnc, wdc, b_dense, out, HID);
}

// round 9
// speedup vs baseline: 1.4853x; 1.4853x over previous
#include <cuda_runtime.h>
#include <cuda_bf16.h>
#include <cuda_fp16.h>
#include <cstdint>
#include <math.h>

#define HID   2048
#define HID3  6144
#define NH    16
#define HD    128
#define BATCH 4
#define SEQ   2048
#define MROWS 8192
#define K2    4096          // storage: [hi | lo] per row (fp16 for GEMM operands)
#define BKG   64            // k-chunk per stage (128B rows)
#define NCHG  64            // fp16 2-term: (Ah+Al)*Bh -> 64 chunks
#define GSTAGES 3
#define STG_BYTES 32768     // 16KB A + 16KB B per stage
#define GEMM_SMEM (GSTAGES*STG_BYTES)   // 98304

// ---------------- scratch (no allocations allowed) ----------------
__device__ __half g_xc[(size_t)MROWS * K2];
__device__ __half g_wqkvc[(size_t)HID3 * K2];
__device__ __half g_wdc[(size_t)HID * K2];
__device__ __half g_attnc[(size_t)MROWS * K2];
// attention operands (bf16, unchanged): [bh][s][256] Q,K ; [bh][256][s] V^T
__device__ __nv_bfloat16 g_qs[(size_t)BATCH * NH * SEQ * 256];
__device__ __nv_bfloat16 g_ks[(size_t)BATCH * NH * SEQ * 256];
__device__ __nv_bfloat16 g_vt[(size_t)BATCH * NH * 256 * SEQ];

// ---------------- helpers ----------------
__device__ __forceinline__ uint32_t s2u(const void* p) {
    uint32_t a;
    asm("{ .reg .u64 t; cvta.to.shared.u64 t, %1; cvt.u32.u64 %0, t; }"
        : "=r"(a) : "l"(p));
    return a;
}
__device__ __forceinline__ void cp16(uint32_t dst, const void* src) {
    asm volatile("cp.async.cg.shared.global [%0], [%1], 16;"
                 :: "r"(dst), "l"(src));
}
__device__ __forceinline__ void ldsm4(uint32_t* r, uint32_t addr) {
    asm volatile("ldmatrix.sync.aligned.m8n8.x4.shared.b16 {%0,%1,%2,%3}, [%4];"
        : "=r"(r[0]), "=r"(r[1]), "=r"(r[2]), "=r"(r[3]) : "r"(addr));
}
// bf16 mma (attention)
__device__ __forceinline__ void mma16816(float* c, const uint32_t* a,
                                         uint32_t b0, uint32_t b1) {
    asm volatile("mma.sync.aligned.m16n8k16.row.col.f32.bf16.bf16.f32 "
        "{%0,%1,%2,%3}, {%4,%5,%6,%7}, {%8,%9}, {%0,%1,%2,%3};"
        : "+f"(c[0]), "+f"(c[1]), "+f"(c[2]), "+f"(c[3])
        : "r"(a[0]), "r"(a[1]), "r"(a[2]), "r"(a[3]), "r"(b0), "r"(b1));
}
// fp16 mma (GEMMs)
__device__ __forceinline__ void mma16816h(float* c, const uint32_t* a,
                                          uint32_t b0, uint32_t b1) {
    asm volatile("mma.sync.aligned.m16n8k16.row.col.f32.f16.f16.f32 "
        "{%0,%1,%2,%3}, {%4,%5,%6,%7}, {%8,%9}, {%0,%1,%2,%3};"
        : "+f"(c[0]), "+f"(c[1]), "+f"(c[2]), "+f"(c[3])
        : "r"(a[0]), "r"(a[1]), "r"(a[2]), "r"(a[3]), "r"(b0), "r"(b1));
}
__device__ __forceinline__ uint32_t pkbf(float lo, float hi) {
    uint32_t r;
    asm("cvt.rn.bf16x2.f32 %0, %1, %2;" : "=r"(r) : "f"(hi), "f"(lo));
    return r;
}
// bf16 split (attention operands)
__device__ __forceinline__ void split1(float v, unsigned short& h, unsigned short& l) {
    __nv_bfloat16 hb = __float2bfloat16(v);
    __nv_bfloat16 lb = __float2bfloat16(v - __bfloat162float(hb));
    h = __bfloat16_as_ushort(hb);
    l = __bfloat16_as_ushort(lb);
}
// fp16 split (GEMM operands)
__device__ __forceinline__ void split1h(float v, unsigned short& h, unsigned short& l) {
    __half hb = __float2half(v);
    __half lb = __float2half(v - __half2float(hb));
    h = __half_as_ushort(hb);
    l = __half_as_ushort(lb);
}

// ---------------- split conversion: fp32[rows][2048] -> fp16[rows][hi|lo] ------
__global__ __launch_bounds__(256) void split_kernel(const float* __restrict__ in,
                                                    __half* __restrict__ out,
                                                    int rows)
{
    size_t i = (size_t)blockIdx.x * 256 + threadIdx.x;
    size_t n4 = (size_t)rows * HID / 4;
    if (i >= n4) return;
    size_t e = i * 4;
    size_t r = e >> 11;
    int    c = (int)(e & 2047);
    float4 v = ((const float4*)in)[i];
    unsigned short h0,h1,h2,h3,l0,l1,l2,l3;
    split1h(v.x,h0,l0); split1h(v.y,h1,l1); split1h(v.z,h2,l2); split1h(v.w,h3,l3);
    __half* o = out + r * K2;
    *(ushort4*)(o + c)       = make_ushort4(h0,h1,h2,h3);
    *(ushort4*)(o + HID + c) = make_ushort4(l0,l1,l2,l3);
}

// ---------------- QKV GEMM with fused operand epilogue (R7 shape) ----------------
__global__ __launch_bounds__(256, 2) void gemm_qkv_kernel(
    const __half* __restrict__ A, const __half* __restrict__ B,
    const float* __restrict__ bias)
{
    extern __shared__ char sm[];
    const uint32_t sb = s2u(sm);
    const int tid = threadIdx.x;
    const int wid = tid >> 5, lane = tid & 31;
    const size_t bm = (size_t)blockIdx.y * 128;
    const size_t bn = (size_t)blockIdx.x * 128;
    const int wm = wid & 3, wn = wid >> 2;

    // fp16 2-term: ch 0..31 : Ah*Bh   ch 32..63 : Al*Bh
    auto issue = [&](int ch) {
        int ach = ch;
        int bch = ch & 31;
        uint32_t st = sb + (ch % GSTAGES) * STG_BYTES;
        const __half* Ab = A + (size_t)ach * BKG;
        const __half* Bb = B + (size_t)bch * BKG;
#pragma unroll
        for (int i = 0; i < 4; i++) {
            int u = i * 256 + tid;
            int r = u >> 3, c = u & 7;
            uint32_t sw = (uint32_t)(r * 128) + (uint32_t)((c * 16) ^ ((r & 7) << 4));
            cp16(st + sw,         Ab + (bm + r) * K2 + c * 8);
            cp16(st + 16384 + sw, Bb + (bn + r) * K2 + c * 8);
        }
        asm volatile("cp.async.commit_group;");
    };

    issue(0);
    issue(1);

    float acc[2][8][4];
#pragma unroll
    for (int mi = 0; mi < 2; mi++)
#pragma unroll
        for (int ni = 0; ni < 8; ni++)
#pragma unroll
            for (int q = 0; q < 4; q++) acc[mi][ni][q] = 0.f;

    const int lm_row = lane & 15;
    const int lm_hi  = (lane >> 4) << 4;

    for (int ch = 0; ch < NCHG; ch++) {
        asm volatile("cp.async.wait_group 1;");
        __syncthreads();
        if (ch + 2 < NCHG) issue(ch + 2);
        uint32_t st = sb + (ch % GSTAGES) * STG_BYTES;
#pragma unroll
        for (int kk = 0; kk < 64; kk += 16) {
            uint32_t a[2][4];
#pragma unroll
            for (int mi = 0; mi < 2; mi++) {
                int row = wm * 32 + mi * 16 + lm_row;
                uint32_t byte = (uint32_t)(kk * 2 + lm_hi);
                ldsm4(a[mi], st + row * 128 + (byte ^ ((row & 7) << 4)));
            }
            uint32_t b[4][4];
#pragma unroll
            for (int g = 0; g < 4; g++) {
                int row = wn * 64 + g * 16 + lm_row;
                uint32_t byte = (uint32_t)(kk * 2 + lm_hi);
                ldsm4(b[g], st + 16384 + row * 128 + (byte ^ ((row & 7) << 4)));
            }
#pragma unroll
            for (int mi = 0; mi < 2; mi++)
#pragma unroll
                for (int ni = 0; ni < 8; ni++) {
                    int g = ni >> 1, h = ni & 1;
                    mma16816h(acc[mi][ni], a[mi], b[g][h], b[g][h + 2]);
                }
        }
    }

    // ---- fused epilogue (writes bf16 attention operands) ----
    const int r0 = wm * 32 + (lane >> 2);
    const int c0 = wn * 64 + (lane & 3) * 2;
    const int sec = (int)(bn >> 11);            // 0=Q 1=K 2=V
    const int hh  = ((int)bn & 2047) >> 7;
    const int b_  = (int)(bm >> 11);
    const int s_base = (int)bm & 2047;
    const size_t bh = (size_t)b_ * NH + hh;
    const float qscale = 0.08838834764831845f;

    if (sec < 2) {
        __nv_bfloat16* dst = (sec == 0) ? g_qs : g_ks;
        const float sc = (sec == 0) ? qscale : 1.f;
#pragma unroll
        for (int mi = 0; mi < 2; mi++)
#pragma unroll
            for (int ni = 0; ni < 8; ni++) {
                int d = c0 + ni * 8;
                float2 bv = *(const float2*)(bias + bn + d);
                float o0 = (acc[mi][ni][0] + bv.x) * sc;
                float o1 = (acc[mi][ni][1] + bv.y) * sc;
                float o2 = (acc[mi][ni][2] + bv.x) * sc;
                float o3 = (acc[mi][ni][3] + bv.y) * sc;
                unsigned short h0,h1,h2,h3,l0,l1,l2,l3;
                split1(o0,h0,l0); split1(o1,h1,l1);
                split1(o2,h2,l2); split1(o3,h3,l3);
                int ra = s_base + r0 + mi * 16;
                __nv_bfloat16* pa = dst + (bh * SEQ + ra) * 256 + d;
                *(ushort2*)pa         = make_ushort2(h0,h1);
                *(ushort2*)(pa + 128) = make_ushort2(l0,l1);
                __nv_bfloat16* pb = pa + 8 * 256;
                *(ushort2*)pb         = make_ushort2(h2,h3);
                *(ushort2*)(pb + 128) = make_ushort2(l2,l3);
            }
    } else {
        // V: transpose through smem, then split to g_vt[bh][d(hi)/(128+d)(lo)][s]
        __syncthreads();
        float* smT = (float*)sm;                 // [128 cols][129]
#pragma unroll
        for (int mi = 0; mi < 2; mi++)
#pragma unroll
            for (int ni = 0; ni < 8; ni++) {
                int d = c0 + ni * 8;
                float2 bv = *(const float2*)(bias + bn + d);
                int ra = r0 + mi * 16;
                smT[d * 129 + ra]           = acc[mi][ni][0] + bv.x;
                smT[(d + 1) * 129 + ra]     = acc[mi][ni][1] + bv.y;
                smT[d * 129 + ra + 8]       = acc[mi][ni][2] + bv.x;
                smT[(d + 1) * 129 + ra + 8] = acc[mi][ni][3] + bv.y;
            }
        __syncthreads();
        const int d = tid >> 1;
        const int sOff = (tid & 1) * 64;
        __nv_bfloat16* ph = g_vt + (bh * 256 + d) * SEQ + s_base + sOff;
        __nv_bfloat16* pl = ph + (size_t)128 * SEQ;
#pragma unroll
        for (int i = 0; i < 16; i++) {
            int s = i * 4;
            float v0 = smT[d * 129 + sOff + s + 0];
            float v1 = smT[d * 129 + sOff + s + 1];
            float v2 = smT[d * 129 + sOff + s + 2];
            float v3 = smT[d * 129 + sOff + s + 3];
            unsigned short h0,h1,h2,h3,l0,l1,l2,l3;
            split1(v0,h0,l0); split1(v1,h1,l1);
            split1(v2,h2,l2); split1(v3,h3,l3);
            *(ushort4*)(ph + s) = make_ushort4(h0,h1,h2,h3);
            *(ushort4*)(pl + s) = make_ushort4(l0,l1,l2,l3);
        }
    }
}

// ---------------- dense GEMM (fp16 2-term, fp32 out) ----------------
__global__ __launch_bounds__(256, 2) void gemm_dense_kernel(
    const __half* __restrict__ A, const __half* __restrict__ B,
    const float* __restrict__ bias, float* __restrict__ C, int Ncols)
{
    extern __shared__ char sm[];
    const uint32_t sb = s2u(sm);
    const int tid = threadIdx.x;
    const int wid = tid >> 5, lane = tid & 31;
    const size_t bm = (size_t)blockIdx.y * 128;
    const size_t bn = (size_t)blockIdx.x * 128;
    const int wm = wid & 3, wn = wid >> 2;

    auto issue = [&](int ch) {
        int ach = ch;
        int bch = ch & 31;
        uint32_t st = sb + (ch % GSTAGES) * STG_BYTES;
        const __half* Ab = A + (size_t)ach * BKG;
        const __half* Bb = B + (size_t)bch * BKG;
#pragma unroll
        for (int i = 0; i < 4; i++) {
            int u = i * 256 + tid;
            int r = u >> 3, c = u & 7;
            uint32_t sw = (uint32_t)(r * 128) + (uint32_t)((c * 16) ^ ((r & 7) << 4));
            cp16(st + sw,         Ab + (bm + r) * K2 + c * 8);
            cp16(st + 16384 + sw, Bb + (bn + r) * K2 + c * 8);
        }
        asm volatile("cp.async.commit_group;");
    };

    issue(0);
    issue(1);

    float acc[2][8][4];
#pragma unroll
    for (int mi = 0; mi < 2; mi++)
#pragma unroll
        for (int ni = 0; ni < 8; ni++)
#pragma unroll
            for (int q = 0; q < 4; q++) acc[mi][ni][q] = 0.f;

    const int lm_row = lane & 15;
    const int lm_hi  = (lane >> 4) << 4;

    for (int ch = 0; ch < NCHG; ch++) {
        asm volatile("cp.async.wait_group 1;");
        __syncthreads();
        if (ch + 2 < NCHG) issue(ch + 2);
        uint32_t st = sb + (ch % GSTAGES) * STG_BYTES;
#pragma unroll
        for (int kk = 0; kk < 64; kk += 16) {
            uint32_t a[2][4];
#pragma unroll
            for (int mi = 0; mi < 2; mi++) {
                int row = wm * 32 + mi * 16 + lm_row;
                uint32_t byte = (uint32_t)(kk * 2 + lm_hi);
                ldsm4(a[mi], st + row * 128 + (byte ^ ((row & 7) << 4)));
            }
            uint32_t b[4][4];
#pragma unroll
            for (int g = 0; g < 4; g++) {
                int row = wn * 64 + g * 16 + lm_row;
                uint32_t byte = (uint32_t)(kk * 2 + lm_hi);
                ldsm4(b[g], st + 16384 + row * 128 + (byte ^ ((row & 7) << 4)));
            }
#pragma unroll
            for (int mi = 0; mi < 2; mi++)
#pragma unroll
                for (int ni = 0; ni < 8; ni++) {
                    int g = ni >> 1, h = ni & 1;
                    mma16816h(acc[mi][ni], a[mi], b[g][h], b[g][h + 2]);
                }
        }
    }

    const int r0 = wm * 32 + (lane >> 2);
    const int c0 = wn * 64 + (lane & 3) * 2;
#pragma unroll
    for (int mi = 0; mi < 2; mi++)
#pragma unroll
        for (int ni = 0; ni < 8; ni++) {
            size_t col = bn + c0 + ni * 8;
            float2 bv = *(const float2*)(bias + col);
            float* p0 = C + (bm + r0 + mi * 16) * (size_t)Ncols + col;
            float* p1 = p0 + 8 * (size_t)Ncols;
            *(float2*)p0 = make_float2(acc[mi][ni][0] + bv.x, acc[mi][ni][1] + bv.y);
            *(float2*)p1 = make_float2(acc[mi][ni][2] + bv.x, acc[mi][ni][3] + bv.y);
        }
}

// ---------------- HMMA causal flash attention (bf16 internals, fp16 out) -------
#define ATTN_SMEM 196608
__global__ __launch_bounds__(256, 1) void attn_hmma_kernel()
{
    extern __shared__ char smc[];
    const uint32_t sb = s2u(smc);
    const int tid = threadIdx.x, w = tid >> 5, lane = tid & 31;
    const int qb = 15 - blockIdx.x, h = blockIdx.y, b = blockIdx.z;
    const int bh = b * NH + h;
    const int nkb = (qb + 1) * 2;
    const int lm_row = lane & 15;
    const int lm_hi  = (lane >> 4) << 4;

    {
        const __nv_bfloat16* Qg = g_qs + ((size_t)bh * SEQ + qb * 128) * 256;
#pragma unroll
        for (int i = 0; i < 16; i++) {
            int u = i * 256 + tid;
            int r = u >> 5, c = u & 31;
            cp16(sb + r * 512 + ((c * 16) ^ ((r & 7) << 4)), Qg + (size_t)r * 256 + c * 8);
        }
    }
    auto issue_kv = [&](int kb) {
        uint32_t kst = sb + 65536 + (kb & 1) * 65536;
#pragma unroll
        for (int i = 0; i < 8; i++) {
            int u = i * 256 + tid;
            int r = u >> 5, c = u & 31;
            cp16(kst + r * 512 + ((c * 16) ^ ((r & 7) << 4)),
                 g_ks + ((size_t)bh * SEQ + kb * 64 + r) * 256 + c * 8);
        }
#pragma unroll
        for (int i = 0; i < 8; i++) {
            int u = i * 256 + tid;
            int r = u >> 3, c = u & 7;
            cp16(kst + 32768 + r * 128 + ((c * 16) ^ ((r & 7) << 4)),
                 g_vt + ((size_t)bh * 256 + r) * SEQ + kb * 64 + c * 8);
        }
        asm volatile("cp.async.commit_group;");
    };
    issue_kv(0);
    if (nkb > 1) issue_kv(1);

    float oacc[16][4];
#pragma unroll
    for (int g = 0; g < 16; g++)
#pragma unroll
        for (int e = 0; e < 4; e++) oacc[g][e] = 0.f;
    float m0 = -1e30f, m1 = -1e30f, lp0 = 0.f, lp1 = 0.f;

    const int row0 = qb * 128 + w * 16 + (lane >> 2);
    const int wrow_max = qb * 128 + w * 16 + 15;

    for (int kb = 0; kb < nkb; kb++) {
        if (kb + 1 < nkb) asm volatile("cp.async.wait_group 1;");
        else              asm volatile("cp.async.wait_group 0;");
        __syncthreads();

        const bool active = (kb * 64) <= wrow_max;
        if (active) {
            const uint32_t kst = sb + 65536 + (kb & 1) * 65536;
            const uint32_t vst = kst + 32768;

            float sacc[8][4];
#pragma unroll
            for (int j = 0; j < 8; j++)
#pragma unroll
                for (int e = 0; e < 4; e++) sacc[j][e] = 0.f;

#pragma unroll
            for (int kk = 0; kk < 8; kk++) {
                const int qrow = w * 16 + lm_row;
                uint32_t qa = sb + qrow * 512 +
                              ((uint32_t)(kk * 32 + lm_hi) ^ ((qrow & 7) << 4));
                uint32_t ah[4], al[4];
                ldsm4(ah, qa);
                ldsm4(al, qa + 256);
#pragma unroll
                for (int g = 0; g < 4; g++) {
                    const int krow = g * 16 + lm_row;
                    uint32_t ka = kst + krow * 512 +
                                  ((uint32_t)(kk * 32 + lm_hi) ^ ((krow & 7) << 4));
                    uint32_t bhh[4], bll[4];
                    ldsm4(bhh, ka);
                    ldsm4(bll, ka + 256);
                    mma16816(sacc[2*g],   ah, bhh[0], bhh[2]);
                    mma16816(sacc[2*g+1], ah, bhh[1], bhh[3]);
                    mma16816(sacc[2*g],   al, bhh[0], bhh[2]);
                    mma16816(sacc[2*g+1], al, bhh[1], bhh[3]);
                    mma16816(sacc[2*g],   ah, bll[0], bll[2]);
                    mma16816(sacc[2*g+1], ah, bll[1], bll[3]);
                }
            }

            float mx0 = -1e30f, mx1 = -1e30f;
#pragma unroll
            for (int j = 0; j < 8; j++) {
                int colb = kb * 64 + j * 8 + (lane & 3) * 2;
                if (colb     > row0)     sacc[j][0] = -1e30f;
                if (colb + 1 > row0)     sacc[j][1] = -1e30f;
                if (colb     > row0 + 8) sacc[j][2] = -1e30f;
                if (colb + 1 > row0 + 8) sacc[j][3] = -1e30f;
                mx0 = fmaxf(mx0, fmaxf(sacc[j][0], sacc[j][1]));
                mx1 = fmaxf(mx1, fmaxf(sacc[j][2], sacc[j][3]));
            }
            mx0 = fmaxf(mx0, __shfl_xor_sync(0xffffffffu, mx0, 1));
            mx0 = fmaxf(mx0, __shfl_xor_sync(0xffffffffu, mx0, 2));
            mx1 = fmaxf(mx1, __shfl_xor_sync(0xffffffffu, mx1, 1));
            mx1 = fmaxf(mx1, __shfl_xor_sync(0xffffffffu, mx1, 2));
            float mn0 = fmaxf(m0, mx0), mn1 = fmaxf(m1, mx1);
            float al0 = __expf(m0 - mn0), al1 = __expf(m1 - mn1);
            m0 = mn0; m1 = mn1;
            float s0 = 0.f, s1 = 0.f;
#pragma unroll
            for (int j = 0; j < 8; j++) {
                sacc[j][0] = __expf(sacc[j][0] - mn0); s0 += sacc[j][0];
                sacc[j][1] = __expf(sacc[j][1] - mn0); s0 += sacc[j][1];
                sacc[j][2] = __expf(sacc[j][2] - mn1); s1 += sacc[j][2];
                sacc[j][3] = __expf(sacc[j][3] - mn1); s1 += sacc[j][3];
            }
            lp0 = lp0 * al0 + s0;
            lp1 = lp1 * al1 + s1;
#pragma unroll
            for (int g = 0; g < 16; g++) {
                oacc[g][0] *= al0; oacc[g][1] *= al0;
                oacc[g][2] *= al1; oacc[g][3] *= al1;
            }

#pragma unroll
            for (int t = 0; t < 4; t++) {
                const int f0 = 2 * t, f1 = 2 * t + 1;
                float ph[8], pl[8];
#pragma unroll
                for (int e = 0; e < 4; e++) {
                    float p0v = sacc[f0][e], p1v = sacc[f1][e];
                    float h0f = __bfloat162float(__float2bfloat16(p0v));
                    float h1f = __bfloat162float(__float2bfloat16(p1v));
                    ph[e]     = h0f; pl[e]     = p0v - h0f;
                    ph[4 + e] = h1f; pl[4 + e] = p1v - h1f;
                }
                uint32_t aPh[4], aPl[4];
                aPh[0] = pkbf(ph[0], ph[1]); aPh[1] = pkbf(ph[2], ph[3]);
                aPh[2] = pkbf(ph[4], ph[5]); aPh[3] = pkbf(ph[6], ph[7]);
                aPl[0] = pkbf(pl[0], pl[1]); aPl[1] = pkbf(pl[2], pl[3]);
                aPl[2] = pkbf(pl[4], pl[5]); aPl[3] = pkbf(pl[6], pl[7]);
#pragma unroll
                for (int g = 0; g < 8; g++) {
                    const int vrow = g * 16 + lm_row;
                    uint32_t va = vst + vrow * 128 +
                                  ((uint32_t)(t * 32 + lm_hi) ^ ((vrow & 7) << 4));
                    uint32_t bhh[4], bll[4];
                    ldsm4(bhh, va);
                    ldsm4(bll, va + 16384);
                    mma16816(oacc[2*g],   aPh, bhh[0], bhh[2]);
                    mma16816(oacc[2*g+1], aPh, bhh[1], bhh[3]);
                    mma16816(oacc[2*g],   aPl, bhh[0], bhh[2]);
                    mma16816(oacc[2*g+1], aPl, bhh[1], bhh[3]);
                    mma16816(oacc[2*g],   aPh, bll[0], bll[2]);
                    mma16816(oacc[2*g+1], aPh, bll[1], bll[3]);
                }
            }
        }
        __syncthreads();
        if (kb + 2 < nkb) issue_kv(kb + 2);
    }

    lp0 += __shfl_xor_sync(0xffffffffu, lp0, 1);
    lp0 += __shfl_xor_sync(0xffffffffu, lp0, 2);
    lp1 += __shfl_xor_sync(0xffffffffu, lp1, 1);
    lp1 += __shfl_xor_sync(0xffffffffu, lp1, 2);
    const float inv0 = 1.f / lp0, inv1 = 1.f / lp1;

    // ---- write O directly as fp16 hi|lo split (g_attnc, dense GEMM input) ----
    const size_t row = (size_t)b * SEQ + qb * 128 + w * 16 + (lane >> 2);
    const int colb = h * 128 + (lane & 3) * 2;
#pragma unroll
    for (int g = 0; g < 16; g++) {
        int col = colb + g * 8;
        float v0 = oacc[g][0] * inv0, v1 = oacc[g][1] * inv0;
        float v2 = oacc[g][2] * inv1, v3 = oacc[g][3] * inv1;
        unsigned short h0,h1,h2,h3,l0,l1,l2,l3;
        split1h(v0,h0,l0); split1h(v1,h1,l1);
        split1h(v2,h2,l2); split1h(v3,h3,l3);
        __half* pa = g_attnc + row * K2 + col;
        *(ushort2*)pa          = make_ushort2(h0,h1);
        *(ushort2*)(pa + HID)  = make_ushort2(l0,l1);
        __half* pb = pa + 8 * K2;
        *(ushort2*)pb          = make_ushort2(h2,h3);
        *(ushort2*)(pb + HID)  = make_ushort2(l2,l3);
    }
}

// ---------------- launch ----------------
extern "C" void kernel_launch(void* const* d_in, const int* in_sizes, int n_in,
                              void* d_out, int out_size)
{
    (void)in_sizes; (void)n_in; (void)out_size;
    const float* x       = (const float*)d_in[0];
    const float* w_qkv   = (const float*)d_in[1];
    const float* b_qkv   = (const float*)d_in[2];
    const float* w_dense = (const float*)d_in[3];
    const float* b_dense = (const float*)d_in[4];
    float* out = (float*)d_out;

    __half *xc, *wqkvc, *wdc, *attnc;
    cudaGetSymbolAddress((void**)&xc, g_xc);
    cudaGetSymbolAddress((void**)&wqkvc, g_wqkvc);
    cudaGetSymbolAddress((void**)&wdc, g_wdc);
    cudaGetSymbolAddress((void**)&attnc, g_attnc);

    cudaFuncSetAttribute(gemm_qkv_kernel,
                         cudaFuncAttributeMaxDynamicSharedMemorySize, GEMM_SMEM);
    cudaFuncSetAttribute(gemm_dense_kernel,
                         cudaFuncAttributeMaxDynamicSharedMemorySize, GEMM_SMEM);
    cudaFuncSetAttribute(attn_hmma_kernel,
                         cudaFuncAttributeMaxDynamicSharedMemorySize, ATTN_SMEM);

    // split conversions (fp32 -> fp16 hi|lo)
    split_kernel<<<(MROWS * HID / 4 + 255) / 256, 256>>>(x, xc, MROWS);
    split_kernel<<<(HID3 * HID / 4 + 255) / 256, 256>>>(w_qkv, wqkvc, HID3);
    split_kernel<<<(HID  * HID / 4 + 255) / 256, 256>>>(w_dense, wdc, HID);

    // 1) QKV GEMM with fused operand-prep epilogue (fp16 2-term)
    gemm_qkv_kernel<<<dim3(HID3 / 128, MROWS / 128), 256, GEMM_SMEM>>>(
        xc, wqkvc, b_qkv);

    // 2) HMMA flash attention (bf16 internals; writes fp16 split)
    attn_hmma_kernel<<<dim3(16, NH, BATCH), 256, ATTN_SMEM>>>();

    // 3) out = attn @ Wdense^T + b (fp16 2-term)
    gemm_dense_kernel<<<dim3(HID / 128, MROWS / 128), 256, GEMM_SMEM>>>(
        attnc, wdc, b_dense, out, HID);
}

// round 10
// speedup vs baseline: 1.6602x; 1.1178x over previous
#include <cuda_runtime.h>
#include <cuda_bf16.h>
#include <cuda_fp16.h>
#include <cstdint>
#include <math.h>

#define HID   2048
#define HID3  6144
#define NH    16
#define HD    128
#define BATCH 4
#define SEQ   2048
#define MROWS 8192
#define K2    4096          // storage: [hi | lo] per row (fp16 GEMM operands)
#define BKG   64            // k-chunk per stage (128B rows)
#define NCHG  64            // fp16 2-term: (Ah+Al)*Bh -> 64 chunks
#define GSTAGES 3
#define STG_BYTES 32768     // 16KB A + 16KB B per stage
#define GEMM_SMEM (GSTAGES*STG_BYTES)   // 98304

// attention smem: Q 64KB + 3 stages x (K 16KB + V 32KB)
#define KV_STG 49152
#define ATTN_SMEM (65536 + 3*KV_STG)    // 212992

// ---------------- scratch (no allocations allowed) ----------------
__device__ __half g_xc[(size_t)MROWS * K2];
__device__ __half g_wqkvc[(size_t)HID3 * K2];
__device__ __half g_wdc[(size_t)HID * K2];
__device__ __half g_attnc[(size_t)MROWS * K2];
// attention operands (fp16): Q [bh][s][256] hi|lo ; K [bh][s][128] hi ; V^T [bh][256][s]
__device__ __half g_qs[(size_t)BATCH * NH * SEQ * 256];
__device__ __half g_ks[(size_t)BATCH * NH * SEQ * 128];
__device__ __half g_vt[(size_t)BATCH * NH * 256 * SEQ];

// ---------------- helpers ----------------
__device__ __forceinline__ uint32_t s2u(const void* p) {
    uint32_t a;
    asm("{ .reg .u64 t; cvta.to.shared.u64 t, %1; cvt.u32.u64 %0, t; }"
        : "=r"(a) : "l"(p));
    return a;
}
__device__ __forceinline__ void cp16(uint32_t dst, const void* src) {
    asm volatile("cp.async.cg.shared.global [%0], [%1], 16;"
                 :: "r"(dst), "l"(src));
}
__device__ __forceinline__ void ldsm4(uint32_t* r, uint32_t addr) {
    asm volatile("ldmatrix.sync.aligned.m8n8.x4.shared.b16 {%0,%1,%2,%3}, [%4];"
        : "=r"(r[0]), "=r"(r[1]), "=r"(r[2]), "=r"(r[3]) : "r"(addr));
}
// fp16 mma
__device__ __forceinline__ void mma16816h(float* c, const uint32_t* a,
                                          uint32_t b0, uint32_t b1) {
    asm volatile("mma.sync.aligned.m16n8k16.row.col.f32.f16.f16.f32 "
        "{%0,%1,%2,%3}, {%4,%5,%6,%7}, {%8,%9}, {%0,%1,%2,%3};"
        : "+f"(c[0]), "+f"(c[1]), "+f"(c[2]), "+f"(c[3])
        : "r"(a[0]), "r"(a[1]), "r"(a[2]), "r"(a[3]), "r"(b0), "r"(b1));
}
// pack two fp32 -> fp16x2 (element0 = lo)
__device__ __forceinline__ uint32_t pkhf(float lo, float hi) {
    uint32_t r;
    asm("cvt.rn.f16x2.f32 %0, %1, %2;" : "=r"(r) : "f"(hi), "f"(lo));
    return r;
}
// fp16 split
__device__ __forceinline__ void split1h(float v, unsigned short& h, unsigned short& l) {
    __half hb = __float2half(v);
    __half lb = __float2half(v - __half2float(hb));
    h = __half_as_ushort(hb);
    l = __half_as_ushort(lb);
}

// ---------------- split conversion: fp32[rows][2048] -> fp16[rows][hi|lo] ------
__global__ __launch_bounds__(256) void split_kernel(const float* __restrict__ in,
                                                    __half* __restrict__ out,
                                                    int rows)
{
    size_t i = (size_t)blockIdx.x * 256 + threadIdx.x;
    size_t n4 = (size_t)rows * HID / 4;
    if (i >= n4) return;
    size_t e = i * 4;
    size_t r = e >> 11;
    int    c = (int)(e & 2047);
    float4 v = ((const float4*)in)[i];
    unsigned short h0,h1,h2,h3,l0,l1,l2,l3;
    split1h(v.x,h0,l0); split1h(v.y,h1,l1); split1h(v.z,h2,l2); split1h(v.w,h3,l3);
    __half* o = out + r * K2;
    *(ushort4*)(o + c)       = make_ushort4(h0,h1,h2,h3);
    *(ushort4*)(o + HID + c) = make_ushort4(l0,l1,l2,l3);
}

// ---------------- QKV GEMM with fused operand epilogue ----------------
__global__ __launch_bounds__(256, 2) void gemm_qkv_kernel(
    const __half* __restrict__ A, const __half* __restrict__ B,
    const float* __restrict__ bias)
{
    extern __shared__ char sm[];
    const uint32_t sb = s2u(sm);
    const int tid = threadIdx.x;
    const int wid = tid >> 5, lane = tid & 31;
    const size_t bm = (size_t)blockIdx.y * 128;
    const size_t bn = (size_t)blockIdx.x * 128;
    const int wm = wid & 3, wn = wid >> 2;

    // fp16 2-term: ch 0..31 : Ah*Bh   ch 32..63 : Al*Bh
    auto issue = [&](int ch) {
        int ach = ch;
        int bch = ch & 31;
        uint32_t st = sb + (ch % GSTAGES) * STG_BYTES;
        const __half* Ab = A + (size_t)ach * BKG;
        const __half* Bb = B + (size_t)bch * BKG;
#pragma unroll
        for (int i = 0; i < 4; i++) {
            int u = i * 256 + tid;
            int r = u >> 3, c = u & 7;
            uint32_t sw = (uint32_t)(r * 128) + (uint32_t)((c * 16) ^ ((r & 7) << 4));
            cp16(st + sw,         Ab + (bm + r) * K2 + c * 8);
            cp16(st + 16384 + sw, Bb + (bn + r) * K2 + c * 8);
        }
        asm volatile("cp.async.commit_group;");
    };

    issue(0);
    issue(1);

    float acc[2][8][4];
#pragma unroll
    for (int mi = 0; mi < 2; mi++)
#pragma unroll
        for (int ni = 0; ni < 8; ni++)
#pragma unroll
            for (int q = 0; q < 4; q++) acc[mi][ni][q] = 0.f;

    const int lm_row = lane & 15;
    const int lm_hi  = (lane >> 4) << 4;

    for (int ch = 0; ch < NCHG; ch++) {
        asm volatile("cp.async.wait_group 1;");
        __syncthreads();
        if (ch + 2 < NCHG) issue(ch + 2);
        uint32_t st = sb + (ch % GSTAGES) * STG_BYTES;
#pragma unroll
        for (int kk = 0; kk < 64; kk += 16) {
            uint32_t a[2][4];
#pragma unroll
            for (int mi = 0; mi < 2; mi++) {
                int row = wm * 32 + mi * 16 + lm_row;
                uint32_t byte = (uint32_t)(kk * 2 + lm_hi);
                ldsm4(a[mi], st + row * 128 + (byte ^ ((row & 7) << 4)));
            }
            uint32_t b[4][4];
#pragma unroll
            for (int g = 0; g < 4; g++) {
                int row = wn * 64 + g * 16 + lm_row;
                uint32_t byte = (uint32_t)(kk * 2 + lm_hi);
                ldsm4(b[g], st + 16384 + row * 128 + (byte ^ ((row & 7) << 4)));
            }
#pragma unroll
            for (int mi = 0; mi < 2; mi++)
#pragma unroll
                for (int ni = 0; ni < 8; ni++) {
                    int g = ni >> 1, h = ni & 1;
                    mma16816h(acc[mi][ni], a[mi], b[g][h], b[g][h + 2]);
                }
        }
    }

    // ---- fused epilogue (writes fp16 attention operands) ----
    const int r0 = wm * 32 + (lane >> 2);
    const int c0 = wn * 64 + (lane & 3) * 2;
    const int sec = (int)(bn >> 11);            // 0=Q 1=K 2=V
    const int hh  = ((int)bn & 2047) >> 7;
    const int b_  = (int)(bm >> 11);
    const int s_base = (int)bm & 2047;
    const size_t bh = (size_t)b_ * NH + hh;
    const float qscale = 0.08838834764831845f;

    if (sec == 0) {
        // Q: scaled, hi|lo at 256 stride
#pragma unroll
        for (int mi = 0; mi < 2; mi++)
#pragma unroll
            for (int ni = 0; ni < 8; ni++) {
                int d = c0 + ni * 8;
                float2 bv = *(const float2*)(bias + bn + d);
                float o0 = (acc[mi][ni][0] + bv.x) * qscale;
                float o1 = (acc[mi][ni][1] + bv.y) * qscale;
                float o2 = (acc[mi][ni][2] + bv.x) * qscale;
                float o3 = (acc[mi][ni][3] + bv.y) * qscale;
                unsigned short h0,h1,h2,h3,l0,l1,l2,l3;
                split1h(o0,h0,l0); split1h(o1,h1,l1);
                split1h(o2,h2,l2); split1h(o3,h3,l3);
                int ra = s_base + r0 + mi * 16;
                __half* pa = g_qs + (bh * SEQ + ra) * 256 + d;
                *(ushort2*)pa         = make_ushort2(h0,h1);
                *(ushort2*)(pa + 128) = make_ushort2(l0,l1);
                __half* pb = pa + 8 * 256;
                *(ushort2*)pb         = make_ushort2(h2,h3);
                *(ushort2*)(pb + 128) = make_ushort2(l2,l3);
            }
    } else if (sec == 1) {
        // K: hi only, 128 stride
#pragma unroll
        for (int mi = 0; mi < 2; mi++)
#pragma unroll
            for (int ni = 0; ni < 8; ni++) {
                int d = c0 + ni * 8;
                float2 bv = *(const float2*)(bias + bn + d);
                unsigned short h0 = __half_as_ushort(__float2half(acc[mi][ni][0] + bv.x));
                unsigned short h1 = __half_as_ushort(__float2half(acc[mi][ni][1] + bv.y));
                unsigned short h2 = __half_as_ushort(__float2half(acc[mi][ni][2] + bv.x));
                unsigned short h3 = __half_as_ushort(__float2half(acc[mi][ni][3] + bv.y));
                int ra = s_base + r0 + mi * 16;
                __half* pa = g_ks + (bh * SEQ + ra) * 128 + d;
                *(ushort2*)pa = make_ushort2(h0,h1);
                __half* pb = pa + 8 * 128;
                *(ushort2*)pb = make_ushort2(h2,h3);
            }
    } else {
        // V: transpose through smem, then split to g_vt[bh][d(hi)/(128+d)(lo)][s]
        __syncthreads();
        float* smT = (float*)sm;                 // [128 cols][129]
#pragma unroll
        for (int mi = 0; mi < 2; mi++)
#pragma unroll
            for (int ni = 0; ni < 8; ni++) {
                int d = c0 + ni * 8;
                float2 bv = *(const float2*)(bias + bn + d);
                int ra = r0 + mi * 16;
                smT[d * 129 + ra]           = acc[mi][ni][0] + bv.x;
                smT[(d + 1) * 129 + ra]     = acc[mi][ni][1] + bv.y;
                smT[d * 129 + ra + 8]       = acc[mi][ni][2] + bv.x;
                smT[(d + 1) * 129 + ra + 8] = acc[mi][ni][3] + bv.y;
            }
        __syncthreads();
        const int d = tid >> 1;
        const int sOff = (tid & 1) * 64;
        __half* ph = g_vt + (bh * 256 + d) * SEQ + s_base + sOff;
        __half* pl = ph + (size_t)128 * SEQ;
#pragma unroll
        for (int i = 0; i < 16; i++) {
            int s = i * 4;
            float v0 = smT[d * 129 + sOff + s + 0];
            float v1 = smT[d * 129 + sOff + s + 1];
            float v2 = smT[d * 129 + sOff + s + 2];
            float v3 = smT[d * 129 + sOff + s + 3];
            unsigned short h0,h1,h2,h3,l0,l1,l2,l3;
            split1h(v0,h0,l0); split1h(v1,h1,l1);
            split1h(v2,h2,l2); split1h(v3,h3,l3);
            *(ushort4*)(ph + s) = make_ushort4(h0,h1,h2,h3);
            *(ushort4*)(pl + s) = make_ushort4(l0,l1,l2,l3);
        }
    }
}

// ---------------- dense GEMM (fp16 2-term, fp32 out) ----------------
__global__ __launch_bounds__(256, 2) void gemm_dense_kernel(
    const __half* __restrict__ A, const __half* __restrict__ B,
    const float* __restrict__ bias, float* __restrict__ C, int Ncols)
{
    extern __shared__ char sm[];
    const uint32_t sb = s2u(sm);
    const int tid = threadIdx.x;
    const int wid = tid >> 5, lane = tid & 31;
    const size_t bm = (size_t)blockIdx.y * 128;
    const size_t bn = (size_t)blockIdx.x * 128;
    const int wm = wid & 3, wn = wid >> 2;

    auto issue = [&](int ch) {
        int ach = ch;
        int bch = ch & 31;
        uint32_t st = sb + (ch % GSTAGES) * STG_BYTES;
        const __half* Ab = A + (size_t)ach * BKG;
        const __half* Bb = B + (size_t)bch * BKG;
#pragma unroll
        for (int i = 0; i < 4; i++) {
            int u = i * 256 + tid;
            int r = u >> 3, c = u & 7;
            uint32_t sw = (uint32_t)(r * 128) + (uint32_t)((c * 16) ^ ((r & 7) << 4));
            cp16(st + sw,         Ab + (bm + r) * K2 + c * 8);
            cp16(st + 16384 + sw, Bb + (bn + r) * K2 + c * 8);
        }
        asm volatile("cp.async.commit_group;");
    };

    issue(0);
    issue(1);

    float acc[2][8][4];
#pragma unroll
    for (int mi = 0; mi < 2; mi++)
#pragma unroll
        for (int ni = 0; ni < 8; ni++)
#pragma unroll
            for (int q = 0; q < 4; q++) acc[mi][ni][q] = 0.f;

    const int lm_row = lane & 15;
    const int lm_hi  = (lane >> 4) << 4;

    for (int ch = 0; ch < NCHG; ch++) {
        asm volatile("cp.async.wait_group 1;");
        __syncthreads();
        if (ch + 2 < NCHG) issue(ch + 2);
        uint32_t st = sb + (ch % GSTAGES) * STG_BYTES;
#pragma unroll
        for (int kk = 0; kk < 64; kk += 16) {
            uint32_t a[2][4];
#pragma unroll
            for (int mi = 0; mi < 2; mi++) {
                int row = wm * 32 + mi * 16 + lm_row;
                uint32_t byte = (uint32_t)(kk * 2 + lm_hi);
                ldsm4(a[mi], st + row * 128 + (byte ^ ((row & 7) << 4)));
            }
            uint32_t b[4][4];
#pragma unroll
            for (int g = 0; g < 4; g++) {
                int row = wn * 64 + g * 16 + lm_row;
                uint32_t byte = (uint32_t)(kk * 2 + lm_hi);
                ldsm4(b[g], st + 16384 + row * 128 + (byte ^ ((row & 7) << 4)));
            }
#pragma unroll
            for (int mi = 0; mi < 2; mi++)
#pragma unroll
                for (int ni = 0; ni < 8; ni++) {
                    int g = ni >> 1, h = ni & 1;
                    mma16816h(acc[mi][ni], a[mi], b[g][h], b[g][h + 2]);
                }
        }
    }

    const int r0 = wm * 32 + (lane >> 2);
    const int c0 = wn * 64 + (lane & 3) * 2;
#pragma unroll
    for (int mi = 0; mi < 2; mi++)
#pragma unroll
        for (int ni = 0; ni < 8; ni++) {
            size_t col = bn + c0 + ni * 8;
            float2 bv = *(const float2*)(bias + col);
            float* p0 = C + (bm + r0 + mi * 16) * (size_t)Ncols + col;
            float* p1 = p0 + 8 * (size_t)Ncols;
            *(float2*)p0 = make_float2(acc[mi][ni][0] + bv.x, acc[mi][ni][1] + bv.y);
            *(float2*)p1 = make_float2(acc[mi][ni][2] + bv.x, acc[mi][ni][3] + bv.y);
        }
}

// ---------------- fp16 HMMA causal flash attention ----------------
// grid (16, NH, BATCH) qb reversed; 256 threads = 8 warps x m16 rows; 3 KV stages.
__global__ __launch_bounds__(256, 1) void attn_hmma_kernel()
{
    extern __shared__ char smc[];
    const uint32_t sb = s2u(smc);
    const int tid = threadIdx.x, w = tid >> 5, lane = tid & 31;
    const int qb = 15 - blockIdx.x, h = blockIdx.y, b = blockIdx.z;
    const int bh = b * NH + h;
    const int nkb = (qb + 1) * 2;
    const int lm_row = lane & 15;
    const int lm_hi  = (lane >> 4) << 4;

    {
        const __half* Qg = g_qs + ((size_t)bh * SEQ + qb * 128) * 256;
#pragma unroll
        for (int i = 0; i < 16; i++) {
            int u = i * 256 + tid;
            int r = u >> 5, c = u & 31;
            cp16(sb + r * 512 + ((c * 16) ^ ((r & 7) << 4)), Qg + (size_t)r * 256 + c * 8);
        }
    }
    auto issue_kv = [&](int kb) {
        uint32_t kst = sb + 65536 + (kb % 3) * KV_STG;
        // K: 64 rows x 256B (hi only)
#pragma unroll
        for (int i = 0; i < 4; i++) {
            int u = i * 256 + tid;
            int r = u >> 4, c = u & 15;
            cp16(kst + r * 256 + ((c * 16) ^ ((r & 7) << 4)),
                 g_ks + ((size_t)bh * SEQ + kb * 64 + r) * 128 + c * 8);
        }
        // V^T: 256 rows x 128B (hi rows 0-127, lo 128-255)
#pragma unroll
        for (int i = 0; i < 8; i++) {
            int u = i * 256 + tid;
            int r = u >> 3, c = u & 7;
            cp16(kst + 16384 + r * 128 + ((c * 16) ^ ((r & 7) << 4)),
                 g_vt + ((size_t)bh * 256 + r) * SEQ + kb * 64 + c * 8);
        }
        asm volatile("cp.async.commit_group;");
    };
    issue_kv(0);
    if (nkb > 1) issue_kv(1);

    float oacc[16][4];
#pragma unroll
    for (int g = 0; g < 16; g++)
#pragma unroll
        for (int e = 0; e < 4; e++) oacc[g][e] = 0.f;
    float m0 = -1e30f, m1 = -1e30f, lp0 = 0.f, lp1 = 0.f;

    const int row0 = qb * 128 + w * 16 + (lane >> 2);
    const int wrow_max = qb * 128 + w * 16 + 15;

    for (int kb = 0; kb < nkb; kb++) {
        if (kb + 1 < nkb) asm volatile("cp.async.wait_group 1;");
        else              asm volatile("cp.async.wait_group 0;");
        __syncthreads();
        if (kb + 2 < nkb) issue_kv(kb + 2);

        const bool active = (kb * 64) <= wrow_max;
        if (active) {
            const uint32_t kst = sb + 65536 + (kb % 3) * KV_STG;
            const uint32_t vst = kst + 16384;

            // ---- S = (Qh + Ql) * Kh ----
            float sacc[8][4];
#pragma unroll
            for (int j = 0; j < 8; j++)
#pragma unroll
                for (int e = 0; e < 4; e++) sacc[j][e] = 0.f;

#pragma unroll
            for (int kk = 0; kk < 8; kk++) {
                const int qrow = w * 16 + lm_row;
                uint32_t qa = sb + qrow * 512 +
                              ((uint32_t)(kk * 32 + lm_hi) ^ ((qrow & 7) << 4));
                uint32_t ah[4], al[4];
                ldsm4(ah, qa);
                ldsm4(al, qa + 256);
#pragma unroll
                for (int g = 0; g < 4; g++) {
                    const int krow = g * 16 + lm_row;
                    uint32_t ka = kst + krow * 256 +
                                  ((uint32_t)(kk * 32 + lm_hi) ^ ((krow & 7) << 4));
                    uint32_t bhh[4];
                    ldsm4(bhh, ka);
                    mma16816h(sacc[2*g],   ah, bhh[0], bhh[2]);
                    mma16816h(sacc[2*g+1], ah, bhh[1], bhh[3]);
                    mma16816h(sacc[2*g],   al, bhh[0], bhh[2]);
                    mma16816h(sacc[2*g+1], al, bhh[1], bhh[3]);
                }
            }

            // ---- mask + online softmax ----
            float mx0 = -1e30f, mx1 = -1e30f;
#pragma unroll
            for (int j = 0; j < 8; j++) {
                int colb = kb * 64 + j * 8 + (lane & 3) * 2;
                if (colb     > row0)     sacc[j][0] = -1e30f;
                if (colb + 1 > row0)     sacc[j][1] = -1e30f;
                if (colb     > row0 + 8) sacc[j][2] = -1e30f;
                if (colb + 1 > row0 + 8) sacc[j][3] = -1e30f;
                mx0 = fmaxf(mx0, fmaxf(sacc[j][0], sacc[j][1]));
                mx1 = fmaxf(mx1, fmaxf(sacc[j][2], sacc[j][3]));
            }
            mx0 = fmaxf(mx0, __shfl_xor_sync(0xffffffffu, mx0, 1));
            mx0 = fmaxf(mx0, __shfl_xor_sync(0xffffffffu, mx0, 2));
            mx1 = fmaxf(mx1, __shfl_xor_sync(0xffffffffu, mx1, 1));
            mx1 = fmaxf(mx1, __shfl_xor_sync(0xffffffffu, mx1, 2));
            float mn0 = fmaxf(m0, mx0), mn1 = fmaxf(m1, mx1);
            float al0 = __expf(m0 - mn0), al1 = __expf(m1 - mn1);
            m0 = mn0; m1 = mn1;
            float s0 = 0.f, s1 = 0.f;
#pragma unroll
            for (int j = 0; j < 8; j++) {
                sacc[j][0] = __expf(sacc[j][0] - mn0); s0 += sacc[j][0];
                sacc[j][1] = __expf(sacc[j][1] - mn0); s0 += sacc[j][1];
                sacc[j][2] = __expf(sacc[j][2] - mn1); s1 += sacc[j][2];
                sacc[j][3] = __expf(sacc[j][3] - mn1); s1 += sacc[j][3];
            }
            lp0 = lp0 * al0 + s0;
            lp1 = lp1 * al1 + s1;
#pragma unroll
            for (int g = 0; g < 16; g++) {
                oacc[g][0] *= al0; oacc[g][1] *= al0;
                oacc[g][2] *= al1; oacc[g][3] *= al1;
            }

            // ---- O += Ph * (Vh + Vl) ----
#pragma unroll
            for (int t = 0; t < 4; t++) {
                const int f0 = 2 * t, f1 = 2 * t + 1;
                uint32_t aPh[4];
                aPh[0] = pkhf(sacc[f0][0], sacc[f0][1]);
                aPh[1] = pkhf(sacc[f0][2], sacc[f0][3]);
                aPh[2] = pkhf(sacc[f1][0], sacc[f1][1]);
                aPh[3] = pkhf(sacc[f1][2], sacc[f1][3]);
#pragma unroll
                for (int g = 0; g < 8; g++) {
                    const int vrow = g * 16 + lm_row;
                    uint32_t va = vst + vrow * 128 +
                                  ((uint32_t)(t * 32 + lm_hi) ^ ((vrow & 7) << 4));
                    uint32_t bhh[4], bll[4];
                    ldsm4(bhh, va);
                    ldsm4(bll, va + 16384);     // lo rows at +128*128B
                    mma16816h(oacc[2*g],   aPh, bhh[0], bhh[2]);
                    mma16816h(oacc[2*g+1], aPh, bhh[1], bhh[3]);
                    mma16816h(oacc[2*g],   aPh, bll[0], bll[2]);
                    mma16816h(oacc[2*g+1], aPh, bll[1], bll[3]);
                }
            }
        }
    }

    lp0 += __shfl_xor_sync(0xffffffffu, lp0, 1);
    lp0 += __shfl_xor_sync(0xffffffffu, lp0, 2);
    lp1 += __shfl_xor_sync(0xffffffffu, lp1, 1);
    lp1 += __shfl_xor_sync(0xffffffffu, lp1, 2);
    const float inv0 = 1.f / lp0, inv1 = 1.f / lp1;

    // ---- write O directly as fp16 hi|lo split (g_attnc) ----
    const size_t row = (size_t)b * SEQ + qb * 128 + w * 16 + (lane >> 2);
    const int colb = h * 128 + (lane & 3) * 2;
#pragma unroll
    for (int g = 0; g < 16; g++) {
        int col = colb + g * 8;
        float v0 = oacc[g][0] * inv0, v1 = oacc[g][1] * inv0;
        float v2 = oacc[g][2] * inv1, v3 = oacc[g][3] * inv1;
        unsigned short h0,h1,h2,h3,l0,l1,l2,l3;
        split1h(v0,h0,l0); split1h(v1,h1,l1);
        split1h(v2,h2,l2); split1h(v3,h3,l3);
        __half* pa = g_attnc + row * K2 + col;
        *(ushort2*)pa          = make_ushort2(h0,h1);
        *(ushort2*)(pa + HID)  = make_ushort2(l0,l1);
        __half* pb = pa + 8 * K2;
        *(ushort2*)pb          = make_ushort2(h2,h3);
        *(ushort2*)(pb + HID)  = make_ushort2(l2,l3);
    }
}

// ---------------- launch ----------------
extern "C" void kernel_launch(void* const* d_in, const int* in_sizes, int n_in,
                              void* d_out, int out_size)
{
    (void)in_sizes; (void)n_in; (void)out_size;
    const float* x       = (const float*)d_in[0];
    const float* w_qkv   = (const float*)d_in[1];
    const float* b_qkv   = (const float*)d_in[2];
    const float* w_dense = (const float*)d_in[3];
    const float* b_dense = (const float*)d_in[4];
    float* out = (float*)d_out;

    __half *xc, *wqkvc, *wdc, *attnc;
    cudaGetSymbolAddress((void**)&xc, g_xc);
    cudaGetSymbolAddress((void**)&wqkvc, g_wqkvc);
    cudaGetSymbolAddress((void**)&wdc, g_wdc);
    cudaGetSymbolAddress((void**)&attnc, g_attnc);

    cudaFuncSetAttribute(gemm_qkv_kernel,
                         cudaFuncAttributeMaxDynamicSharedMemorySize, GEMM_SMEM);
    cudaFuncSetAttribute(gemm_dense_kernel,
                         cudaFuncAttributeMaxDynamicSharedMemorySize, GEMM_SMEM);
    cudaFuncSetAttribute(attn_hmma_kernel,
                         cudaFuncAttributeMaxDynamicSharedMemorySize, ATTN_SMEM);

    // split conversions (fp32 -> fp16 hi|lo)
    split_kernel<<<(MROWS * HID / 4 + 255) / 256, 256>>>(x, xc, MROWS);
    split_kernel<<<(HID3 * HID / 4 + 255) / 256, 256>>>(w_qkv, wqkvc, HID3);
    split_kernel<<<(HID  * HID / 4 + 255) / 256, 256>>>(w_dense, wdc, HID);

    // 1) QKV GEMM with fused operand-prep epilogue (fp16 2-term)
    gemm_qkv_kernel<<<dim3(HID3 / 128, MROWS / 128), 256, GEMM_SMEM>>>(
        xc, wqkvc, b_qkv);

    // 2) fp16 HMMA flash attention (writes fp16 split)
    attn_hmma_kernel<<<dim3(16, NH, BATCH), 256, ATTN_SMEM>>>();

    // 3) out = attn @ Wdense^T + b (fp16 2-term)
    gemm_dense_kernel<<<dim3(HID / 128, MROWS / 128), 256, GEMM_SMEM>>>(
        attnc, wdc, b_dense, out, HID);
}

// round 11
// speedup vs baseline: 2.5352x; 1.5270x over previous
#include <cuda_runtime.h>
#include <cuda_bf16.h>
#include <cuda_fp16.h>
#include <cstdint>
#include <math.h>

#define HID   2048
#define HID3  6144
#define NH    16
#define HD    128
#define BATCH 4
#define SEQ   2048
#define MROWS 8192
#define KH    2048          // fp16 operand storage (hi only)
#define BKG   64            // k-chunk per stage (128B rows)
#define NCHG  32            // pure fp16: 32 chunks
#define GSTAGES 3
#define STG_BYTES 32768     // 16KB A + 16KB B per stage
#define GEMM_SMEM (GSTAGES*STG_BYTES)   // 98304

// attention smem: Q 64KB + 3 stages x (K 16KB + V 32KB)
#define KV_STG 49152
#define ATTN_SMEM (65536 + 3*KV_STG)    // 212992

// ---------------- scratch (no allocations allowed) ----------------
__device__ __half g_xc[(size_t)MROWS * KH];
__device__ __half g_wqkvc[(size_t)HID3 * KH];
__device__ __half g_wdc[(size_t)HID * KH];
__device__ __half g_attnc[(size_t)MROWS * KH];
// attention operands (fp16): Q [bh][s][256] hi|lo ; K [bh][s][128] hi ; V^T [bh][256][s]
__device__ __half g_qs[(size_t)BATCH * NH * SEQ * 256];
__device__ __half g_ks[(size_t)BATCH * NH * SEQ * 128];
__device__ __half g_vt[(size_t)BATCH * NH * 256 * SEQ];

// ---------------- helpers ----------------
__device__ __forceinline__ uint32_t s2u(const void* p) {
    uint32_t a;
    asm("{ .reg .u64 t; cvta.to.shared.u64 t, %1; cvt.u32.u64 %0, t; }"
        : "=r"(a) : "l"(p));
    return a;
}
__device__ __forceinline__ void cp16(uint32_t dst, const void* src) {
    asm volatile("cp.async.cg.shared.global [%0], [%1], 16;"
                 :: "r"(dst), "l"(src));
}
__device__ __forceinline__ void ldsm4(uint32_t* r, uint32_t addr) {
    asm volatile("ldmatrix.sync.aligned.m8n8.x4.shared.b16 {%0,%1,%2,%3}, [%4];"
        : "=r"(r[0]), "=r"(r[1]), "=r"(r[2]), "=r"(r[3]) : "r"(addr));
}
// fp16 mma
__device__ __forceinline__ void mma16816h(float* c, const uint32_t* a,
                                          uint32_t b0, uint32_t b1) {
    asm volatile("mma.sync.aligned.m16n8k16.row.col.f32.f16.f16.f32 "
        "{%0,%1,%2,%3}, {%4,%5,%6,%7}, {%8,%9}, {%0,%1,%2,%3};"
        : "+f"(c[0]), "+f"(c[1]), "+f"(c[2]), "+f"(c[3])
        : "r"(a[0]), "r"(a[1]), "r"(a[2]), "r"(a[3]), "r"(b0), "r"(b1));
}
// pack two fp32 -> fp16x2 (element0 = lo)
__device__ __forceinline__ uint32_t pkhf(float lo, float hi) {
    uint32_t r;
    asm("cvt.rn.f16x2.f32 %0, %1, %2;" : "=r"(r) : "f"(hi), "f"(lo));
    return r;
}
// fp16 split
__device__ __forceinline__ void split1h(float v, unsigned short& h, unsigned short& l) {
    __half hb = __float2half(v);
    __half lb = __float2half(v - __half2float(hb));
    h = __half_as_ushort(hb);
    l = __half_as_ushort(lb);
}

// ---------------- convert: fp32[rows][2048] -> fp16[rows][2048] ----------------
__global__ __launch_bounds__(256) void cvt_kernel(const float* __restrict__ in,
                                                  __half* __restrict__ out,
                                                  int rows)
{
    size_t i = (size_t)blockIdx.x * 256 + threadIdx.x;
    size_t n4 = (size_t)rows * HID / 4;
    if (i >= n4) return;
    float4 v = ((const float4*)in)[i];
    ushort4 o = make_ushort4(__half_as_ushort(__float2half(v.x)),
                             __half_as_ushort(__float2half(v.y)),
                             __half_as_ushort(__float2half(v.z)),
                             __half_as_ushort(__float2half(v.w)));
    ((ushort4*)out)[i] = o;
}

// ---------------- QKV GEMM with fused operand epilogue (pure fp16) -------------
__global__ __launch_bounds__(256, 2) void gemm_qkv_kernel(
    const __half* __restrict__ A, const __half* __restrict__ B,
    const float* __restrict__ bias)
{
    extern __shared__ char sm[];
    const uint32_t sb = s2u(sm);
    const int tid = threadIdx.x;
    const int wid = tid >> 5, lane = tid & 31;
    const size_t bm = (size_t)blockIdx.y * 128;
    const size_t bn = (size_t)blockIdx.x * 128;
    const int wm = wid & 3, wn = wid >> 2;

    auto issue = [&](int ch) {
        uint32_t st = sb + (ch % GSTAGES) * STG_BYTES;
        const __half* Ab = A + (size_t)ch * BKG;
        const __half* Bb = B + (size_t)ch * BKG;
#pragma unroll
        for (int i = 0; i < 4; i++) {
            int u = i * 256 + tid;
            int r = u >> 3, c = u & 7;
            uint32_t sw = (uint32_t)(r * 128) + (uint32_t)((c * 16) ^ ((r & 7) << 4));
            cp16(st + sw,         Ab + (bm + r) * KH + c * 8);
            cp16(st + 16384 + sw, Bb + (bn + r) * KH + c * 8);
        }
        asm volatile("cp.async.commit_group;");
    };

    issue(0);
    issue(1);

    float acc[2][8][4];
#pragma unroll
    for (int mi = 0; mi < 2; mi++)
#pragma unroll
        for (int ni = 0; ni < 8; ni++)
#pragma unroll
            for (int q = 0; q < 4; q++) acc[mi][ni][q] = 0.f;

    const int lm_row = lane & 15;
    const int lm_hi  = (lane >> 4) << 4;

    for (int ch = 0; ch < NCHG; ch++) {
        asm volatile("cp.async.wait_group 1;");
        __syncthreads();
        if (ch + 2 < NCHG) issue(ch + 2);
        uint32_t st = sb + (ch % GSTAGES) * STG_BYTES;
#pragma unroll
        for (int kk = 0; kk < 64; kk += 16) {
            uint32_t a[2][4];
#pragma unroll
            for (int mi = 0; mi < 2; mi++) {
                int row = wm * 32 + mi * 16 + lm_row;
                uint32_t byte = (uint32_t)(kk * 2 + lm_hi);
                ldsm4(a[mi], st + row * 128 + (byte ^ ((row & 7) << 4)));
            }
            uint32_t b[4][4];
#pragma unroll
            for (int g = 0; g < 4; g++) {
                int row = wn * 64 + g * 16 + lm_row;
                uint32_t byte = (uint32_t)(kk * 2 + lm_hi);
                ldsm4(b[g], st + 16384 + row * 128 + (byte ^ ((row & 7) << 4)));
            }
#pragma unroll
            for (int mi = 0; mi < 2; mi++)
#pragma unroll
                for (int ni = 0; ni < 8; ni++) {
                    int g = ni >> 1, h = ni & 1;
                    mma16816h(acc[mi][ni], a[mi], b[g][h], b[g][h + 2]);
                }
        }
    }

    // ---- fused epilogue (writes fp16 attention operands) ----
    const int r0 = wm * 32 + (lane >> 2);
    const int c0 = wn * 64 + (lane & 3) * 2;
    const int sec = (int)(bn >> 11);            // 0=Q 1=K 2=V
    const int hh  = ((int)bn & 2047) >> 7;
    const int b_  = (int)(bm >> 11);
    const int s_base = (int)bm & 2047;
    const size_t bh = (size_t)b_ * NH + hh;
    const float qscale = 0.08838834764831845f;

    if (sec == 0) {
        // Q: scaled, hi|lo at 256 stride
#pragma unroll
        for (int mi = 0; mi < 2; mi++)
#pragma unroll
            for (int ni = 0; ni < 8; ni++) {
                int d = c0 + ni * 8;
                float2 bv = *(const float2*)(bias + bn + d);
                float o0 = (acc[mi][ni][0] + bv.x) * qscale;
                float o1 = (acc[mi][ni][1] + bv.y) * qscale;
                float o2 = (acc[mi][ni][2] + bv.x) * qscale;
                float o3 = (acc[mi][ni][3] + bv.y) * qscale;
                unsigned short h0,h1,h2,h3,l0,l1,l2,l3;
                split1h(o0,h0,l0); split1h(o1,h1,l1);
                split1h(o2,h2,l2); split1h(o3,h3,l3);
                int ra = s_base + r0 + mi * 16;
                __half* pa = g_qs + (bh * SEQ + ra) * 256 + d;
                *(ushort2*)pa         = make_ushort2(h0,h1);
                *(ushort2*)(pa + 128) = make_ushort2(l0,l1);
                __half* pb = pa + 8 * 256;
                *(ushort2*)pb         = make_ushort2(h2,h3);
                *(ushort2*)(pb + 128) = make_ushort2(l2,l3);
            }
    } else if (sec == 1) {
        // K: hi only, 128 stride
#pragma unroll
        for (int mi = 0; mi < 2; mi++)
#pragma unroll
            for (int ni = 0; ni < 8; ni++) {
                int d = c0 + ni * 8;
                float2 bv = *(const float2*)(bias + bn + d);
                unsigned short h0 = __half_as_ushort(__float2half(acc[mi][ni][0] + bv.x));
                unsigned short h1 = __half_as_ushort(__float2half(acc[mi][ni][1] + bv.y));
                unsigned short h2 = __half_as_ushort(__float2half(acc[mi][ni][2] + bv.x));
                unsigned short h3 = __half_as_ushort(__float2half(acc[mi][ni][3] + bv.y));
                int ra = s_base + r0 + mi * 16;
                __half* pa = g_ks + (bh * SEQ + ra) * 128 + d;
                *(ushort2*)pa = make_ushort2(h0,h1);
                __half* pb = pa + 8 * 128;
                *(ushort2*)pb = make_ushort2(h2,h3);
            }
    } else {
        // V: transpose through smem, then split to g_vt[bh][d(hi)/(128+d)(lo)][s]
        __syncthreads();
        float* smT = (float*)sm;                 // [128 cols][129]
#pragma unroll
        for (int mi = 0; mi < 2; mi++)
#pragma unroll
            for (int ni = 0; ni < 8; ni++) {
                int d = c0 + ni * 8;
                float2 bv = *(const float2*)(bias + bn + d);
                int ra = r0 + mi * 16;
                smT[d * 129 + ra]           = acc[mi][ni][0] + bv.x;
                smT[(d + 1) * 129 + ra]     = acc[mi][ni][1] + bv.y;
                smT[d * 129 + ra + 8]       = acc[mi][ni][2] + bv.x;
                smT[(d + 1) * 129 + ra + 8] = acc[mi][ni][3] + bv.y;
            }
        __syncthreads();
        const int d = tid >> 1;
        const int sOff = (tid & 1) * 64;
        __half* ph = g_vt + (bh * 256 + d) * SEQ + s_base + sOff;
        __half* pl = ph + (size_t)128 * SEQ;
#pragma unroll
        for (int i = 0; i < 16; i++) {
            int s = i * 4;
            float v0 = smT[d * 129 + sOff + s + 0];
            float v1 = smT[d * 129 + sOff + s + 1];
            float v2 = smT[d * 129 + sOff + s + 2];
            float v3 = smT[d * 129 + sOff + s + 3];
            unsigned short h0,h1,h2,h3,l0,l1,l2,l3;
            split1h(v0,h0,l0); split1h(v1,h1,l1);
            split1h(v2,h2,l2); split1h(v3,h3,l3);
            *(ushort4*)(ph + s) = make_ushort4(h0,h1,h2,h3);
            *(ushort4*)(pl + s) = make_ushort4(l0,l1,l2,l3);
        }
    }
}

// ---------------- dense GEMM (pure fp16, fp32 out) ----------------
__global__ __launch_bounds__(256, 2) void gemm_dense_kernel(
    const __half* __restrict__ A, const __half* __restrict__ B,
    const float* __restrict__ bias, float* __restrict__ C, int Ncols)
{
    extern __shared__ char sm[];
    const uint32_t sb = s2u(sm);
    const int tid = threadIdx.x;
    const int wid = tid >> 5, lane = tid & 31;
    const size_t bm = (size_t)blockIdx.y * 128;
    const size_t bn = (size_t)blockIdx.x * 128;
    const int wm = wid & 3, wn = wid >> 2;

    auto issue = [&](int ch) {
        uint32_t st = sb + (ch % GSTAGES) * STG_BYTES;
        const __half* Ab = A + (size_t)ch * BKG;
        const __half* Bb = B + (size_t)ch * BKG;
#pragma unroll
        for (int i = 0; i < 4; i++) {
            int u = i * 256 + tid;
            int r = u >> 3, c = u & 7;
            uint32_t sw = (uint32_t)(r * 128) + (uint32_t)((c * 16) ^ ((r & 7) << 4));
            cp16(st + sw,         Ab + (bm + r) * KH + c * 8);
            cp16(st + 16384 + sw, Bb + (bn + r) * KH + c * 8);
        }
        asm volatile("cp.async.commit_group;");
    };

    issue(0);
    issue(1);

    float acc[2][8][4];
#pragma unroll
    for (int mi = 0; mi < 2; mi++)
#pragma unroll
        for (int ni = 0; ni < 8; ni++)
#pragma unroll
            for (int q = 0; q < 4; q++) acc[mi][ni][q] = 0.f;

    const int lm_row = lane & 15;
    const int lm_hi  = (lane >> 4) << 4;

    for (int ch = 0; ch < NCHG; ch++) {
        asm volatile("cp.async.wait_group 1;");
        __syncthreads();
        if (ch + 2 < NCHG) issue(ch + 2);
        uint32_t st = sb + (ch % GSTAGES) * STG_BYTES;
#pragma unroll
        for (int kk = 0; kk < 64; kk += 16) {
            uint32_t a[2][4];
#pragma unroll
            for (int mi = 0; mi < 2; mi++) {
                int row = wm * 32 + mi * 16 + lm_row;
                uint32_t byte = (uint32_t)(kk * 2 + lm_hi);
                ldsm4(a[mi], st + row * 128 + (byte ^ ((row & 7) << 4)));
            }
            uint32_t b[4][4];
#pragma unroll
            for (int g = 0; g < 4; g++) {
                int row = wn * 64 + g * 16 + lm_row;
                uint32_t byte = (uint32_t)(kk * 2 + lm_hi);
                ldsm4(b[g], st + 16384 + row * 128 + (byte ^ ((row & 7) << 4)));
            }
#pragma unroll
            for (int mi = 0; mi < 2; mi++)
#pragma unroll
                for (int ni = 0; ni < 8; ni++) {
                    int g = ni >> 1, h = ni & 1;
                    mma16816h(acc[mi][ni], a[mi], b[g][h], b[g][h + 2]);
                }
        }
    }

    const int r0 = wm * 32 + (lane >> 2);
    const int c0 = wn * 64 + (lane & 3) * 2;
#pragma unroll
    for (int mi = 0; mi < 2; mi++)
#pragma unroll
        for (int ni = 0; ni < 8; ni++) {
            size_t col = bn + c0 + ni * 8;
            float2 bv = *(const float2*)(bias + col);
            float* p0 = C + (bm + r0 + mi * 16) * (size_t)Ncols + col;
            float* p1 = p0 + 8 * (size_t)Ncols;
            *(float2*)p0 = make_float2(acc[mi][ni][0] + bv.x, acc[mi][ni][1] + bv.y);
            *(float2*)p1 = make_float2(acc[mi][ni][2] + bv.x, acc[mi][ni][3] + bv.y);
        }
}

// ---------------- fp16 HMMA causal flash attention (unchanged) ----------------
__global__ __launch_bounds__(256, 1) void attn_hmma_kernel()
{
    extern __shared__ char smc[];
    const uint32_t sb = s2u(smc);
    const int tid = threadIdx.x, w = tid >> 5, lane = tid & 31;
    const int qb = 15 - blockIdx.x, h = blockIdx.y, b = blockIdx.z;
    const int bh = b * NH + h;
    const int nkb = (qb + 1) * 2;
    const int lm_row = lane & 15;
    const int lm_hi  = (lane >> 4) << 4;

    {
        const __half* Qg = g_qs + ((size_t)bh * SEQ + qb * 128) * 256;
#pragma unroll
        for (int i = 0; i < 16; i++) {
            int u = i * 256 + tid;
            int r = u >> 5, c = u & 31;
            cp16(sb + r * 512 + ((c * 16) ^ ((r & 7) << 4)), Qg + (size_t)r * 256 + c * 8);
        }
    }
    auto issue_kv = [&](int kb) {
        uint32_t kst = sb + 65536 + (kb % 3) * KV_STG;
#pragma unroll
        for (int i = 0; i < 4; i++) {
            int u = i * 256 + tid;
            int r = u >> 4, c = u & 15;
            cp16(kst + r * 256 + ((c * 16) ^ ((r & 7) << 4)),
                 g_ks + ((size_t)bh * SEQ + kb * 64 + r) * 128 + c * 8);
        }
#pragma unroll
        for (int i = 0; i < 8; i++) {
            int u = i * 256 + tid;
            int r = u >> 3, c = u & 7;
            cp16(kst + 16384 + r * 128 + ((c * 16) ^ ((r & 7) << 4)),
                 g_vt + ((size_t)bh * 256 + r) * SEQ + kb * 64 + c * 8);
        }
        asm volatile("cp.async.commit_group;");
    };
    issue_kv(0);
    if (nkb > 1) issue_kv(1);

    float oacc[16][4];
#pragma unroll
    for (int g = 0; g < 16; g++)
#pragma unroll
        for (int e = 0; e < 4; e++) oacc[g][e] = 0.f;
    float m0 = -1e30f, m1 = -1e30f, lp0 = 0.f, lp1 = 0.f;

    const int row0 = qb * 128 + w * 16 + (lane >> 2);
    const int wrow_max = qb * 128 + w * 16 + 15;

    for (int kb = 0; kb < nkb; kb++) {
        if (kb + 1 < nkb) asm volatile("cp.async.wait_group 1;");
        else              asm volatile("cp.async.wait_group 0;");
        __syncthreads();
        if (kb + 2 < nkb) issue_kv(kb + 2);

        const bool active = (kb * 64) <= wrow_max;
        if (active) {
            const uint32_t kst = sb + 65536 + (kb % 3) * KV_STG;
            const uint32_t vst = kst + 16384;

            // ---- S = (Qh + Ql) * Kh ----
            float sacc[8][4];
#pragma unroll
            for (int j = 0; j < 8; j++)
#pragma unroll
                for (int e = 0; e < 4; e++) sacc[j][e] = 0.f;

#pragma unroll
            for (int kk = 0; kk < 8; kk++) {
                const int qrow = w * 16 + lm_row;
                uint32_t qa = sb + qrow * 512 +
                              ((uint32_t)(kk * 32 + lm_hi) ^ ((qrow & 7) << 4));
                uint32_t ah[4], al[4];
                ldsm4(ah, qa);
                ldsm4(al, qa + 256);
#pragma unroll
                for (int g = 0; g < 4; g++) {
                    const int krow = g * 16 + lm_row;
                    uint32_t ka = kst + krow * 256 +
                                  ((uint32_t)(kk * 32 + lm_hi) ^ ((krow & 7) << 4));
                    uint32_t bhh[4];
                    ldsm4(bhh, ka);
                    mma16816h(sacc[2*g],   ah, bhh[0], bhh[2]);
                    mma16816h(sacc[2*g+1], ah, bhh[1], bhh[3]);
                    mma16816h(sacc[2*g],   al, bhh[0], bhh[2]);
                    mma16816h(sacc[2*g+1], al, bhh[1], bhh[3]);
                }
            }

            // ---- mask + online softmax ----
            float mx0 = -1e30f, mx1 = -1e30f;
#pragma unroll
            for (int j = 0; j < 8; j++) {
                int colb = kb * 64 + j * 8 + (lane & 3) * 2;
                if (colb     > row0)     sacc[j][0] = -1e30f;
                if (colb + 1 > row0)     sacc[j][1] = -1e30f;
                if (colb     > row0 + 8) sacc[j][2] = -1e30f;
                if (colb + 1 > row0 + 8) sacc[j][3] = -1e30f;
                mx0 = fmaxf(mx0, fmaxf(sacc[j][0], sacc[j][1]));
                mx1 = fmaxf(mx1, fmaxf(sacc[j][2], sacc[j][3]));
            }
            mx0 = fmaxf(mx0, __shfl_xor_sync(0xffffffffu, mx0, 1));
            mx0 = fmaxf(mx0, __shfl_xor_sync(0xffffffffu, mx0, 2));
            mx1 = fmaxf(mx1, __shfl_xor_sync(0xffffffffu, mx1, 1));
            mx1 = fmaxf(mx1, __shfl_xor_sync(0xffffffffu, mx1, 2));
            float mn0 = fmaxf(m0, mx0), mn1 = fmaxf(m1, mx1);
            float al0 = __expf(m0 - mn0), al1 = __expf(m1 - mn1);
            m0 = mn0; m1 = mn1;
            float s0 = 0.f, s1 = 0.f;
#pragma unroll
            for (int j = 0; j < 8; j++) {
                sacc[j][0] = __expf(sacc[j][0] - mn0); s0 += sacc[j][0];
                sacc[j][1] = __expf(sacc[j][1] - mn0); s0 += sacc[j][1];
                sacc[j][2] = __expf(sacc[j][2] - mn1); s1 += sacc[j][2];
                sacc[j][3] = __expf(sacc[j][3] - mn1); s1 += sacc[j][3];
            }
            lp0 = lp0 * al0 + s0;
            lp1 = lp1 * al1 + s1;
#pragma unroll
            for (int g = 0; g < 16; g++) {
                oacc[g][0] *= al0; oacc[g][1] *= al0;
                oacc[g][2] *= al1; oacc[g][3] *= al1;
            }

            // ---- O += Ph * (Vh + Vl) ----
#pragma unroll
            for (int t = 0; t < 4; t++) {
                const int f0 = 2 * t, f1 = 2 * t + 1;
                uint32_t aPh[4];
                aPh[0] = pkhf(sacc[f0][0], sacc[f0][1]);
                aPh[1] = pkhf(sacc[f0][2], sacc[f0][3]);
                aPh[2] = pkhf(sacc[f1][0], sacc[f1][1]);
                aPh[3] = pkhf(sacc[f1][2], sacc[f1][3]);
#pragma unroll
                for (int g = 0; g < 8; g++) {
                    const int vrow = g * 16 + lm_row;
                    uint32_t va = vst + vrow * 128 +
                                  ((uint32_t)(t * 32 + lm_hi) ^ ((vrow & 7) << 4));
                    uint32_t bhh[4], bll[4];
                    ldsm4(bhh, va);
                    ldsm4(bll, va + 16384);
                    mma16816h(oacc[2*g],   aPh, bhh[0], bhh[2]);
                    mma16816h(oacc[2*g+1], aPh, bhh[1], bhh[3]);
                    mma16816h(oacc[2*g],   aPh, bll[0], bll[2]);
                    mma16816h(oacc[2*g+1], aPh, bll[1], bll[3]);
                }
            }
        }
    }

    lp0 += __shfl_xor_sync(0xffffffffu, lp0, 1);
    lp0 += __shfl_xor_sync(0xffffffffu, lp0, 2);
    lp1 += __shfl_xor_sync(0xffffffffu, lp1, 1);
    lp1 += __shfl_xor_sync(0xffffffffu, lp1, 2);
    const float inv0 = 1.f / lp0, inv1 = 1.f / lp1;

    // ---- write O as plain fp16 (g_attnc, dense GEMM input) ----
    const size_t row = (size_t)b * SEQ + qb * 128 + w * 16 + (lane >> 2);
    const int colb = h * 128 + (lane & 3) * 2;
#pragma unroll
    for (int g = 0; g < 16; g++) {
        int col = colb + g * 8;
        unsigned short h0 = __half_as_ushort(__float2half(oacc[g][0] * inv0));
        unsigned short h1 = __half_as_ushort(__float2half(oacc[g][1] * inv0));
        unsigned short h2 = __half_as_ushort(__float2half(oacc[g][2] * inv1));
        unsigned short h3 = __half_as_ushort(__float2half(oacc[g][3] * inv1));
        __half* pa = g_attnc + row * KH + col;
        *(ushort2*)pa            = make_ushort2(h0,h1);
        *(ushort2*)(pa + 8 * KH) = make_ushort2(h2,h3);
    }
}

// ---------------- launch ----------------
extern "C" void kernel_launch(void* const* d_in, const int* in_sizes, int n_in,
                              void* d_out, int out_size)
{
    (void)in_sizes; (void)n_in; (void)out_size;
    const float* x       = (const float*)d_in[0];
    const float* w_qkv   = (const float*)d_in[1];
    const float* b_qkv   = (const float*)d_in[2];
    const float* w_dense = (const float*)d_in[3];
    const float* b_dense = (const float*)d_in[4];
    float* out = (float*)d_out;

    __half *xc, *wqkvc, *wdc, *attnc;
    cudaGetSymbolAddress((void**)&xc, g_xc);
    cudaGetSymbolAddress((void**)&wqkvc, g_wqkvc);
    cudaGetSymbolAddress((void**)&wdc, g_wdc);
    cudaGetSymbolAddress((void**)&attnc, g_attnc);

    cudaFuncSetAttribute(gemm_qkv_kernel,
                         cudaFuncAttributeMaxDynamicSharedMemorySize, GEMM_SMEM);
    cudaFuncSetAttribute(gemm_dense_kernel,
                         cudaFuncAttributeMaxDynamicSharedMemorySize, GEMM_SMEM);
    cudaFuncSetAttribute(attn_hmma_kernel,
                         cudaFuncAttributeMaxDynamicSharedMemorySize, ATTN_SMEM);

    // converts (fp32 -> fp16)
    cvt_kernel<<<(MROWS * HID / 4 + 255) / 256, 256>>>(x, xc, MROWS);
    cvt_kernel<<<(HID3 * HID / 4 + 255) / 256, 256>>>(w_qkv, wqkvc, HID3);
    cvt_kernel<<<(HID  * HID / 4 + 255) / 256, 256>>>(w_dense, wdc, HID);

    // 1) QKV GEMM with fused operand-prep epilogue (pure fp16)
    gemm_qkv_kernel<<<dim3(HID3 / 128, MROWS / 128), 256, GEMM_SMEM>>>(
        xc, wqkvc, b_qkv);

    // 2) fp16 HMMA flash attention
    attn_hmma_kernel<<<dim3(16, NH, BATCH), 256, ATTN_SMEM>>>();

    // 3) out = attn @ Wdense^T + b (pure fp16)
    gemm_dense_kernel<<<dim3(HID / 128, MROWS / 128), 256, GEMM_SMEM>>>(
        attnc, wdc, b_dense, out, HID);
}

// round 12
// speedup vs baseline: 3.0098x; 1.1872x over previous
#include <cuda_runtime.h>
#include <cuda_bf16.h>
#include <cuda_fp16.h>
#include <cstdint>
#include <math.h>

#define HID   2048
#define HID3  6144
#define NH    16
#define HD    128
#define BATCH 4
#define SEQ   2048
#define MROWS 8192
#define KH    2048          // fp16 operand storage
#define BKG   64            // k-chunk per stage (128B rows)
#define NCHG  32            // pure fp16: 32 chunks
#define GSTAGES 3
#define STG_BYTES 32768     // 16KB A + 16KB B per stage
#define GEMM_SMEM (GSTAGES*STG_BYTES)   // 98304

// attention smem: Q 32KB + 3 stages x (K 16KB + V 16KB)
#define KV_STG 32768
#define ATTN_SMEM (32768 + 3*KV_STG)    // 131072

// ---------------- scratch (no allocations allowed) ----------------
__device__ __half g_xc[(size_t)MROWS * KH];
__device__ __half g_wqkvc[(size_t)HID3 * KH];
__device__ __half g_wdc[(size_t)HID * KH];
__device__ __half g_attnc[(size_t)MROWS * KH];
// attention operands (fp16 hi-only): Q,K [bh][s][128] ; V^T [bh][128][s]
__device__ __half g_qs[(size_t)BATCH * NH * SEQ * 128];
__device__ __half g_ks[(size_t)BATCH * NH * SEQ * 128];
__device__ __half g_vt[(size_t)BATCH * NH * 128 * SEQ];

// ---------------- helpers ----------------
__device__ __forceinline__ uint32_t s2u(const void* p) {
    uint32_t a;
    asm("{ .reg .u64 t; cvta.to.shared.u64 t, %1; cvt.u32.u64 %0, t; }"
        : "=r"(a) : "l"(p));
    return a;
}
__device__ __forceinline__ void cp16(uint32_t dst, const void* src) {
    asm volatile("cp.async.cg.shared.global [%0], [%1], 16;"
                 :: "r"(dst), "l"(src));
}
__device__ __forceinline__ void ldsm4(uint32_t* r, uint32_t addr) {
    asm volatile("ldmatrix.sync.aligned.m8n8.x4.shared.b16 {%0,%1,%2,%3}, [%4];"
        : "=r"(r[0]), "=r"(r[1]), "=r"(r[2]), "=r"(r[3]) : "r"(addr));
}
// fp16 mma
__device__ __forceinline__ void mma16816h(float* c, const uint32_t* a,
                                          uint32_t b0, uint32_t b1) {
    asm volatile("mma.sync.aligned.m16n8k16.row.col.f32.f16.f16.f32 "
        "{%0,%1,%2,%3}, {%4,%5,%6,%7}, {%8,%9}, {%0,%1,%2,%3};"
        : "+f"(c[0]), "+f"(c[1]), "+f"(c[2]), "+f"(c[3])
        : "r"(a[0]), "r"(a[1]), "r"(a[2]), "r"(a[3]), "r"(b0), "r"(b1));
}
// pack two fp32 -> fp16x2 (element0 = lo)
__device__ __forceinline__ uint32_t pkhf(float lo, float hi) {
    uint32_t r;
    asm("cvt.rn.f16x2.f32 %0, %1, %2;" : "=r"(r) : "f"(hi), "f"(lo));
    return r;
}

// ---------------- convert: fp32[rows][2048] -> fp16[rows][2048] ----------------
__global__ __launch_bounds__(256) void cvt_kernel(const float* __restrict__ in,
                                                  __half* __restrict__ out,
                                                  int rows)
{
    size_t i = (size_t)blockIdx.x * 256 + threadIdx.x;
    size_t n4 = (size_t)rows * HID / 4;
    if (i >= n4) return;
    float4 v = ((const float4*)in)[i];
    ushort4 o = make_ushort4(__half_as_ushort(__float2half(v.x)),
                             __half_as_ushort(__float2half(v.y)),
                             __half_as_ushort(__float2half(v.z)),
                             __half_as_ushort(__float2half(v.w)));
    ((ushort4*)out)[i] = o;
}

// ---------------- QKV GEMM with fused operand epilogue (pure fp16) -------------
__global__ __launch_bounds__(256, 2) void gemm_qkv_kernel(
    const __half* __restrict__ A, const __half* __restrict__ B,
    const float* __restrict__ bias)
{
    extern __shared__ char sm[];
    const uint32_t sb = s2u(sm);
    const int tid = threadIdx.x;
    const int wid = tid >> 5, lane = tid & 31;
    const size_t bm = (size_t)blockIdx.y * 128;
    const size_t bn = (size_t)blockIdx.x * 128;
    const int wm = wid & 3, wn = wid >> 2;

    auto issue = [&](int ch) {
        uint32_t st = sb + (ch % GSTAGES) * STG_BYTES;
        const __half* Ab = A + (size_t)ch * BKG;
        const __half* Bb = B + (size_t)ch * BKG;
#pragma unroll
        for (int i = 0; i < 4; i++) {
            int u = i * 256 + tid;
            int r = u >> 3, c = u & 7;
            uint32_t sw = (uint32_t)(r * 128) + (uint32_t)((c * 16) ^ ((r & 7) << 4));
            cp16(st + sw,         Ab + (bm + r) * KH + c * 8);
            cp16(st + 16384 + sw, Bb + (bn + r) * KH + c * 8);
        }
        asm volatile("cp.async.commit_group;");
    };

    issue(0);
    issue(1);

    float acc[2][8][4];
#pragma unroll
    for (int mi = 0; mi < 2; mi++)
#pragma unroll
        for (int ni = 0; ni < 8; ni++)
#pragma unroll
            for (int q = 0; q < 4; q++) acc[mi][ni][q] = 0.f;

    const int lm_row = lane & 15;
    const int lm_hi  = (lane >> 4) << 4;

    for (int ch = 0; ch < NCHG; ch++) {
        asm volatile("cp.async.wait_group 1;");
        __syncthreads();
        if (ch + 2 < NCHG) issue(ch + 2);
        uint32_t st = sb + (ch % GSTAGES) * STG_BYTES;
#pragma unroll
        for (int kk = 0; kk < 64; kk += 16) {
            uint32_t a[2][4];
#pragma unroll
            for (int mi = 0; mi < 2; mi++) {
                int row = wm * 32 + mi * 16 + lm_row;
                uint32_t byte = (uint32_t)(kk * 2 + lm_hi);
                ldsm4(a[mi], st + row * 128 + (byte ^ ((row & 7) << 4)));
            }
            uint32_t b[4][4];
#pragma unroll
            for (int g = 0; g < 4; g++) {
                int row = wn * 64 + g * 16 + lm_row;
                uint32_t byte = (uint32_t)(kk * 2 + lm_hi);
                ldsm4(b[g], st + 16384 + row * 128 + (byte ^ ((row & 7) << 4)));
            }
#pragma unroll
            for (int mi = 0; mi < 2; mi++)
#pragma unroll
                for (int ni = 0; ni < 8; ni++) {
                    int g = ni >> 1, h = ni & 1;
                    mma16816h(acc[mi][ni], a[mi], b[g][h], b[g][h + 2]);
                }
        }
    }

    // ---- fused epilogue (writes fp16 attention operands, all hi-only) ----
    const int r0 = wm * 32 + (lane >> 2);
    const int c0 = wn * 64 + (lane & 3) * 2;
    const int sec = (int)(bn >> 11);            // 0=Q 1=K 2=V
    const int hh  = ((int)bn & 2047) >> 7;
    const int b_  = (int)(bm >> 11);
    const int s_base = (int)bm & 2047;
    const size_t bh = (size_t)b_ * NH + hh;
    const float qscale = 0.08838834764831845f;

    if (sec < 2) {
        __half* dst = (sec == 0) ? g_qs : g_ks;
        const float sc = (sec == 0) ? qscale : 1.f;
#pragma unroll
        for (int mi = 0; mi < 2; mi++)
#pragma unroll
            for (int ni = 0; ni < 8; ni++) {
                int d = c0 + ni * 8;
                float2 bv = *(const float2*)(bias + bn + d);
                unsigned short h0 = __half_as_ushort(__float2half((acc[mi][ni][0] + bv.x) * sc));
                unsigned short h1 = __half_as_ushort(__float2half((acc[mi][ni][1] + bv.y) * sc));
                unsigned short h2 = __half_as_ushort(__float2half((acc[mi][ni][2] + bv.x) * sc));
                unsigned short h3 = __half_as_ushort(__float2half((acc[mi][ni][3] + bv.y) * sc));
                int ra = s_base + r0 + mi * 16;
                __half* pa = dst + (bh * SEQ + ra) * 128 + d;
                *(ushort2*)pa             = make_ushort2(h0,h1);
                *(ushort2*)(pa + 8 * 128) = make_ushort2(h2,h3);
            }
    } else {
        // V: transpose through smem -> g_vt[bh][d][s] (hi only)
        __syncthreads();
        float* smT = (float*)sm;                 // [128 cols][129]
#pragma unroll
        for (int mi = 0; mi < 2; mi++)
#pragma unroll
            for (int ni = 0; ni < 8; ni++) {
                int d = c0 + ni * 8;
                float2 bv = *(const float2*)(bias + bn + d);
                int ra = r0 + mi * 16;
                smT[d * 129 + ra]           = acc[mi][ni][0] + bv.x;
                smT[(d + 1) * 129 + ra]     = acc[mi][ni][1] + bv.y;
                smT[d * 129 + ra + 8]       = acc[mi][ni][2] + bv.x;
                smT[(d + 1) * 129 + ra + 8] = acc[mi][ni][3] + bv.y;
            }
        __syncthreads();
        const int d = tid >> 1;
        const int sOff = (tid & 1) * 64;
        __half* ph = g_vt + (bh * 128 + d) * SEQ + s_base + sOff;
#pragma unroll
        for (int i = 0; i < 16; i++) {
            int s = i * 4;
            ushort4 o = make_ushort4(
                __half_as_ushort(__float2half(smT[d * 129 + sOff + s + 0])),
                __half_as_ushort(__float2half(smT[d * 129 + sOff + s + 1])),
                __half_as_ushort(__float2half(smT[d * 129 + sOff + s + 2])),
                __half_as_ushort(__float2half(smT[d * 129 + sOff + s + 3])));
            *(ushort4*)(ph + s) = o;
        }
    }
}

// ---------------- dense GEMM (pure fp16, fp32 out) ----------------
__global__ __launch_bounds__(256, 2) void gemm_dense_kernel(
    const __half* __restrict__ A, const __half* __restrict__ B,
    const float* __restrict__ bias, float* __restrict__ C, int Ncols)
{
    extern __shared__ char sm[];
    const uint32_t sb = s2u(sm);
    const int tid = threadIdx.x;
    const int wid = tid >> 5, lane = tid & 31;
    const size_t bm = (size_t)blockIdx.y * 128;
    const size_t bn = (size_t)blockIdx.x * 128;
    const int wm = wid & 3, wn = wid >> 2;

    auto issue = [&](int ch) {
        uint32_t st = sb + (ch % GSTAGES) * STG_BYTES;
        const __half* Ab = A + (size_t)ch * BKG;
        const __half* Bb = B + (size_t)ch * BKG;
#pragma unroll
        for (int i = 0; i < 4; i++) {
            int u = i * 256 + tid;
            int r = u >> 3, c = u & 7;
            uint32_t sw = (uint32_t)(r * 128) + (uint32_t)((c * 16) ^ ((r & 7) << 4));
            cp16(st + sw,         Ab + (bm + r) * KH + c * 8);
            cp16(st + 16384 + sw, Bb + (bn + r) * KH + c * 8);
        }
        asm volatile("cp.async.commit_group;");
    };

    issue(0);
    issue(1);

    float acc[2][8][4];
#pragma unroll
    for (int mi = 0; mi < 2; mi++)
#pragma unroll
        for (int ni = 0; ni < 8; ni++)
#pragma unroll
            for (int q = 0; q < 4; q++) acc[mi][ni][q] = 0.f;

    const int lm_row = lane & 15;
    const int lm_hi  = (lane >> 4) << 4;

    for (int ch = 0; ch < NCHG; ch++) {
        asm volatile("cp.async.wait_group 1;");
        __syncthreads();
        if (ch + 2 < NCHG) issue(ch + 2);
        uint32_t st = sb + (ch % GSTAGES) * STG_BYTES;
#pragma unroll
        for (int kk = 0; kk < 64; kk += 16) {
            uint32_t a[2][4];
#pragma unroll
            for (int mi = 0; mi < 2; mi++) {
                int row = wm * 32 + mi * 16 + lm_row;
                uint32_t byte = (uint32_t)(kk * 2 + lm_hi);
                ldsm4(a[mi], st + row * 128 + (byte ^ ((row & 7) << 4)));
            }
            uint32_t b[4][4];
#pragma unroll
            for (int g = 0; g < 4; g++) {
                int row = wn * 64 + g * 16 + lm_row;
                uint32_t byte = (uint32_t)(kk * 2 + lm_hi);
                ldsm4(b[g], st + 16384 + row * 128 + (byte ^ ((row & 7) << 4)));
            }
#pragma unroll
            for (int mi = 0; mi < 2; mi++)
#pragma unroll
                for (int ni = 0; ni < 8; ni++) {
                    int g = ni >> 1, h = ni & 1;
                    mma16816h(acc[mi][ni], a[mi], b[g][h], b[g][h + 2]);
                }
        }
    }

    const int r0 = wm * 32 + (lane >> 2);
    const int c0 = wn * 64 + (lane & 3) * 2;
#pragma unroll
    for (int mi = 0; mi < 2; mi++)
#pragma unroll
        for (int ni = 0; ni < 8; ni++) {
            size_t col = bn + c0 + ni * 8;
            float2 bv = *(const float2*)(bias + col);
            float* p0 = C + (bm + r0 + mi * 16) * (size_t)Ncols + col;
            float* p1 = p0 + 8 * (size_t)Ncols;
            *(float2*)p0 = make_float2(acc[mi][ni][0] + bv.x, acc[mi][ni][1] + bv.y);
            *(float2*)p1 = make_float2(acc[mi][ni][2] + bv.x, acc[mi][ni][3] + bv.y);
        }
}

// ---------------- fp16 HMMA causal flash attention (1-term QK and PV) ----------
// grid (16, NH, BATCH) qb reversed; 256 threads = 8 warps x m16 rows; 3 KV stages.
__global__ __launch_bounds__(256, 1) void attn_hmma_kernel()
{
    extern __shared__ char smc[];
    const uint32_t sb = s2u(smc);
    const int tid = threadIdx.x, w = tid >> 5, lane = tid & 31;
    const int qb = 15 - blockIdx.x, h = blockIdx.y, b = blockIdx.z;
    const int bh = b * NH + h;
    const int nkb = (qb + 1) * 2;
    const int lm_row = lane & 15;
    const int lm_hi  = (lane >> 4) << 4;

    // Q tile: 128 rows x 256B
    {
        const __half* Qg = g_qs + ((size_t)bh * SEQ + qb * 128) * 128;
#pragma unroll
        for (int i = 0; i < 8; i++) {
            int u = i * 256 + tid;
            int r = u >> 4, c = u & 15;
            cp16(sb + r * 256 + ((c * 16) ^ ((r & 7) << 4)), Qg + (size_t)r * 128 + c * 8);
        }
    }
    auto issue_kv = [&](int kb) {
        uint32_t kst = sb + 32768 + (kb % 3) * KV_STG;
        // K: 64 rows x 256B
#pragma unroll
        for (int i = 0; i < 4; i++) {
            int u = i * 256 + tid;
            int r = u >> 4, c = u & 15;
            cp16(kst + r * 256 + ((c * 16) ^ ((r & 7) << 4)),
                 g_ks + ((size_t)bh * SEQ + kb * 64 + r) * 128 + c * 8);
        }
        // V^T: 128 rows x 128B
#pragma unroll
        for (int i = 0; i < 4; i++) {
            int u = i * 256 + tid;
            int r = u >> 3, c = u & 7;
            cp16(kst + 16384 + r * 128 + ((c * 16) ^ ((r & 7) << 4)),
                 g_vt + ((size_t)bh * 128 + r) * SEQ + kb * 64 + c * 8);
        }
        asm volatile("cp.async.commit_group;");
    };
    issue_kv(0);
    if (nkb > 1) issue_kv(1);

    float oacc[16][4];
#pragma unroll
    for (int g = 0; g < 16; g++)
#pragma unroll
        for (int e = 0; e < 4; e++) oacc[g][e] = 0.f;
    float m0 = -1e30f, m1 = -1e30f, lp0 = 0.f, lp1 = 0.f;

    const int row0 = qb * 128 + w * 16 + (lane >> 2);
    const int wrow_max = qb * 128 + w * 16 + 15;

    for (int kb = 0; kb < nkb; kb++) {
        if (kb + 1 < nkb) asm volatile("cp.async.wait_group 1;");
        else              asm volatile("cp.async.wait_group 0;");
        __syncthreads();
        if (kb + 2 < nkb) issue_kv(kb + 2);

        const bool active = (kb * 64) <= wrow_max;
        if (active) {
            const uint32_t kst = sb + 32768 + (kb % 3) * KV_STG;
            const uint32_t vst = kst + 16384;

            // ---- S = Q * K^T (1-term fp16) ----
            float sacc[8][4];
#pragma unroll
            for (int j = 0; j < 8; j++)
#pragma unroll
                for (int e = 0; e < 4; e++) sacc[j][e] = 0.f;

#pragma unroll
            for (int kk = 0; kk < 8; kk++) {
                const int qrow = w * 16 + lm_row;
                uint32_t qa = sb + qrow * 256 +
                              ((uint32_t)(kk * 32 + lm_hi) ^ ((qrow & 7) << 4));
                uint32_t ah[4];
                ldsm4(ah, qa);
#pragma unroll
                for (int g = 0; g < 4; g++) {
                    const int krow = g * 16 + lm_row;
                    uint32_t ka = kst + krow * 256 +
                                  ((uint32_t)(kk * 32 + lm_hi) ^ ((krow & 7) << 4));
                    uint32_t bhh[4];
                    ldsm4(bhh, ka);
                    mma16816h(sacc[2*g],   ah, bhh[0], bhh[2]);
                    mma16816h(sacc[2*g+1], ah, bhh[1], bhh[3]);
                }
            }

            // ---- mask + online softmax ----
            float mx0 = -1e30f, mx1 = -1e30f;
#pragma unroll
            for (int j = 0; j < 8; j++) {
                int colb = kb * 64 + j * 8 + (lane & 3) * 2;
                if (colb     > row0)     sacc[j][0] = -1e30f;
                if (colb + 1 > row0)     sacc[j][1] = -1e30f;
                if (colb     > row0 + 8) sacc[j][2] = -1e30f;
                if (colb + 1 > row0 + 8) sacc[j][3] = -1e30f;
                mx0 = fmaxf(mx0, fmaxf(sacc[j][0], sacc[j][1]));
                mx1 = fmaxf(mx1, fmaxf(sacc[j][2], sacc[j][3]));
            }
            mx0 = fmaxf(mx0, __shfl_xor_sync(0xffffffffu, mx0, 1));
            mx0 = fmaxf(mx0, __shfl_xor_sync(0xffffffffu, mx0, 2));
            mx1 = fmaxf(mx1, __shfl_xor_sync(0xffffffffu, mx1, 1));
            mx1 = fmaxf(mx1, __shfl_xor_sync(0xffffffffu, mx1, 2));
            float mn0 = fmaxf(m0, mx0), mn1 = fmaxf(m1, mx1);
            float al0 = __expf(m0 - mn0), al1 = __expf(m1 - mn1);
            m0 = mn0; m1 = mn1;
            float s0 = 0.f, s1 = 0.f;
#pragma unroll
            for (int j = 0; j < 8; j++) {
                sacc[j][0] = __expf(sacc[j][0] - mn0); s0 += sacc[j][0];
                sacc[j][1] = __expf(sacc[j][1] - mn0); s0 += sacc[j][1];
                sacc[j][2] = __expf(sacc[j][2] - mn1); s1 += sacc[j][2];
                sacc[j][3] = __expf(sacc[j][3] - mn1); s1 += sacc[j][3];
            }
            lp0 = lp0 * al0 + s0;
            lp1 = lp1 * al1 + s1;
#pragma unroll
            for (int g = 0; g < 16; g++) {
                oacc[g][0] *= al0; oacc[g][1] *= al0;
                oacc[g][2] *= al1; oacc[g][3] *= al1;
            }

            // ---- O += P * V (1-term fp16) ----
#pragma unroll
            for (int t = 0; t < 4; t++) {
                const int f0 = 2 * t, f1 = 2 * t + 1;
                uint32_t aPh[4];
                aPh[0] = pkhf(sacc[f0][0], sacc[f0][1]);
                aPh[1] = pkhf(sacc[f0][2], sacc[f0][3]);
                aPh[2] = pkhf(sacc[f1][0], sacc[f1][1]);
                aPh[3] = pkhf(sacc[f1][2], sacc[f1][3]);
#pragma unroll
                for (int g = 0; g < 8; g++) {
                    const int vrow = g * 16 + lm_row;
                    uint32_t va = vst + vrow * 128 +
                                  ((uint32_t)(t * 32 + lm_hi) ^ ((vrow & 7) << 4));
                    uint32_t bhh[4];
                    ldsm4(bhh, va);
                    mma16816h(oacc[2*g],   aPh, bhh[0], bhh[2]);
                    mma16816h(oacc[2*g+1], aPh, bhh[1], bhh[3]);
                }
            }
        }
    }

    lp0 += __shfl_xor_sync(0xffffffffu, lp0, 1);
    lp0 += __shfl_xor_sync(0xffffffffu, lp0, 2);
    lp1 += __shfl_xor_sync(0xffffffffu, lp1, 1);
    lp1 += __shfl_xor_sync(0xffffffffu, lp1, 2);
    const float inv0 = 1.f / lp0, inv1 = 1.f / lp1;

    // ---- write O as plain fp16 (g_attnc, dense GEMM input) ----
    const size_t row = (size_t)b * SEQ + qb * 128 + w * 16 + (lane >> 2);
    const int colb = h * 128 + (lane & 3) * 2;
#pragma unroll
    for (int g = 0; g < 16; g++) {
        int col = colb + g * 8;
        unsigned short h0 = __half_as_ushort(__float2half(oacc[g][0] * inv0));
        unsigned short h1 = __half_as_ushort(__float2half(oacc[g][1] * inv0));
        unsigned short h2 = __half_as_ushort(__float2half(oacc[g][2] * inv1));
        unsigned short h3 = __half_as_ushort(__float2half(oacc[g][3] * inv1));
        __half* pa = g_attnc + row * KH + col;
        *(ushort2*)pa            = make_ushort2(h0,h1);
        *(ushort2*)(pa + 8 * KH) = make_ushort2(h2,h3);
    }
}

// ---------------- launch ----------------
extern "C" void kernel_launch(void* const* d_in, const int* in_sizes, int n_in,
                              void* d_out, int out_size)
{
    (void)in_sizes; (void)n_in; (void)out_size;
    const float* x       = (const float*)d_in[0];
    const float* w_qkv   = (const float*)d_in[1];
    const float* b_qkv   = (const float*)d_in[2];
    const float* w_dense = (const float*)d_in[3];
    const float* b_dense = (const float*)d_in[4];
    float* out = (float*)d_out;

    __half *xc, *wqkvc, *wdc, *attnc;
    cudaGetSymbolAddress((void**)&xc, g_xc);
    cudaGetSymbolAddress((void**)&wqkvc, g_wqkvc);
    cudaGetSymbolAddress((void**)&wdc, g_wdc);
    cudaGetSymbolAddress((void**)&attnc, g_attnc);

    cudaFuncSetAttribute(gemm_qkv_kernel,
                         cudaFuncAttributeMaxDynamicSharedMemorySize, GEMM_SMEM);
    cudaFuncSetAttribute(gemm_dense_kernel,
                         cudaFuncAttributeMaxDynamicSharedMemorySize, GEMM_SMEM);
    cudaFuncSetAttribute(attn_hmma_kernel,
                         cudaFuncAttributeMaxDynamicSharedMemorySize, ATTN_SMEM);

    // converts (fp32 -> fp16)
    cvt_kernel<<<(MROWS * HID / 4 + 255) / 256, 256>>>(x, xc, MROWS);
    cvt_kernel<<<(HID3 * HID / 4 + 255) / 256, 256>>>(w_qkv, wqkvc, HID3);
    cvt_kernel<<<(HID  * HID / 4 + 255) / 256, 256>>>(w_dense, wdc, HID);

    // 1) QKV GEMM with fused operand-prep epilogue (pure fp16)
    gemm_qkv_kernel<<<dim3(HID3 / 128, MROWS / 128), 256, GEMM_SMEM>>>(
        xc, wqkvc, b_qkv);

    // 2) fp16 HMMA flash attention (1-term QK and PV)
    attn_hmma_kernel<<<dim3(16, NH, BATCH), 256, ATTN_SMEM>>>();

    // 3) out = attn @ Wdense^T + b (pure fp16)
    gemm_dense_kernel<<<dim3(HID / 128, MROWS / 128), 256, GEMM_SMEM>>>(
        attnc, wdc, b_dense, out, HID);
}

// round 13
// speedup vs baseline: 3.0644x; 1.0181x over previous
#include <cuda_runtime.h>
#include <cuda_bf16.h>
#include <cuda_fp16.h>
#include <cstdint>
#include <math.h>

#define HID   2048
#define HID3  6144
#define NH    16
#define HD    128
#define BATCH 4
#define SEQ   2048
#define MROWS 8192
#define KH    2048          // fp16 operand storage
#define BKG   64            // k-chunk per stage (128B rows)
#define NCHG  32            // pure fp16: 32 chunks
#define GSTAGES 3
#define STG_BYTES 32768     // 16KB A + 16KB B per stage
#define GEMM_SMEM (GSTAGES*STG_BYTES)   // 98304

// attention smem: Q 32KB + 3 stages x (K 16KB + V 16KB)
#define KV_STG 32768
#define ATTN_SMEM (32768 + 3*KV_STG)    // 131072

// ---------------- scratch (no allocations allowed) ----------------
__device__ __half g_xc[(size_t)MROWS * KH];
__device__ __half g_wqkvc[(size_t)HID3 * KH];
__device__ __half g_wdc[(size_t)HID * KH];
__device__ __half g_attnc[(size_t)MROWS * KH];
// attention operands (fp16 hi-only): Q,K [bh][s][128] ; V^T [bh][128][s]
__device__ __half g_qs[(size_t)BATCH * NH * SEQ * 128];
__device__ __half g_ks[(size_t)BATCH * NH * SEQ * 128];
__device__ __half g_vt[(size_t)BATCH * NH * 128 * SEQ];

// ---------------- helpers ----------------
__device__ __forceinline__ uint32_t s2u(const void* p) {
    uint32_t a;
    asm("{ .reg .u64 t; cvta.to.shared.u64 t, %1; cvt.u32.u64 %0, t; }"
        : "=r"(a) : "l"(p));
    return a;
}
__device__ __forceinline__ void cp16(uint32_t dst, const void* src) {
    asm volatile("cp.async.cg.shared.global [%0], [%1], 16;"
                 :: "r"(dst), "l"(src));
}
__device__ __forceinline__ void ldsm4(uint32_t* r, uint32_t addr) {
    asm volatile("ldmatrix.sync.aligned.m8n8.x4.shared.b16 {%0,%1,%2,%3}, [%4];"
        : "=r"(r[0]), "=r"(r[1]), "=r"(r[2]), "=r"(r[3]) : "r"(addr));
}
// fp16 mma
__device__ __forceinline__ void mma16816h(float* c, const uint32_t* a,
                                          uint32_t b0, uint32_t b1) {
    asm volatile("mma.sync.aligned.m16n8k16.row.col.f32.f16.f16.f32 "
        "{%0,%1,%2,%3}, {%4,%5,%6,%7}, {%8,%9}, {%0,%1,%2,%3};"
        : "+f"(c[0]), "+f"(c[1]), "+f"(c[2]), "+f"(c[3])
        : "r"(a[0]), "r"(a[1]), "r"(a[2]), "r"(a[3]), "r"(b0), "r"(b1));
}
// pack two fp32 -> fp16x2 (element0 = lo)
__device__ __forceinline__ uint32_t pkhf(float lo, float hi) {
    uint32_t r;
    asm("cvt.rn.f16x2.f32 %0, %1, %2;" : "=r"(r) : "f"(hi), "f"(lo));
    return r;
}

// ---------------- fused convert: all three fp32 -> fp16 tensors -----------------
#define N4_X   ((size_t)MROWS * HID / 4)
#define N4_WQ  ((size_t)HID3 * HID / 4)
#define N4_WD  ((size_t)HID * HID / 4)
__global__ __launch_bounds__(256) void cvt_all_kernel(const float* __restrict__ x,
                                                      const float* __restrict__ wq,
                                                      const float* __restrict__ wd)
{
    size_t i = (size_t)blockIdx.x * 256 + threadIdx.x;
    const float* in;
    __half* out;
    size_t rel;
    if (i < N4_X)              { in = x;  out = g_xc;    rel = i; }
    else if (i < N4_X + N4_WQ) { in = wq; out = g_wqkvc; rel = i - N4_X; }
    else if (i < N4_X + N4_WQ + N4_WD) { in = wd; out = g_wdc; rel = i - N4_X - N4_WQ; }
    else return;
    float4 v = ((const float4*)in)[rel];
    ushort4 o = make_ushort4(__half_as_ushort(__float2half(v.x)),
                             __half_as_ushort(__float2half(v.y)),
                             __half_as_ushort(__float2half(v.z)),
                             __half_as_ushort(__float2half(v.w)));
    ((ushort4*)out)[rel] = o;
}

// ============= GEMM mainloop (double-buffered register fragments) ==============
// Defines/fills: acc[2][8][4]. Requires locals: sb, tid, wid, lane, wm, wn, bm, bn.
#define GEMM_MAINLOOP(A_, B_)                                                      \
    auto issue = [&](int ch) {                                                     \
        uint32_t st = sb + (ch % GSTAGES) * STG_BYTES;                             \
        const __half* Ab = (A_) + (size_t)ch * BKG;                                \
        const __half* Bb = (B_) + (size_t)ch * BKG;                                \
        _Pragma("unroll")                                                          \
        for (int i = 0; i < 4; i++) {                                              \
            int u = i * 256 + tid;                                                 \
            int r = u >> 3, c = u & 7;                                             \
            uint32_t sw = (uint32_t)(r * 128) + (uint32_t)((c * 16) ^ ((r & 7) << 4)); \
            cp16(st + sw,         Ab + (bm + r) * KH + c * 8);                     \
            cp16(st + 16384 + sw, Bb + (bn + r) * KH + c * 8);                     \
        }                                                                          \
        asm volatile("cp.async.commit_group;");                                    \
    };                                                                             \
    issue(0);                                                                      \
    issue(1);                                                                      \
    float acc[2][8][4];                                                            \
    _Pragma("unroll")                                                              \
    for (int mi = 0; mi < 2; mi++)                                                 \
        _Pragma("unroll")                                                          \
        for (int ni = 0; ni < 8; ni++)                                             \
            _Pragma("unroll")                                                      \
            for (int q = 0; q < 4; q++) acc[mi][ni][q] = 0.f;                      \
    const int lm_row = lane & 15;                                                  \
    const int lm_hi  = (lane >> 4) << 4;                                           \
    uint32_t afr[2][2][4], bfr[2][4][4];                                           \
    auto load_frags = [&](uint32_t st, int kk, uint32_t (*af)[4], uint32_t (*bf)[4]) { \
        _Pragma("unroll")                                                          \
        for (int mi = 0; mi < 2; mi++) {                                           \
            int row = wm * 32 + mi * 16 + lm_row;                                  \
            uint32_t byte = (uint32_t)(kk * 32 + lm_hi);                           \
            ldsm4(af[mi], st + row * 128 + (byte ^ ((row & 7) << 4)));             \
        }                                                                          \
        _Pragma("unroll")                                                          \
        for (int g = 0; g < 4; g++) {                                              \
            int row = wn * 64 + g * 16 + lm_row;                                   \
            uint32_t byte = (uint32_t)(kk * 32 + lm_hi);                           \
            ldsm4(bf[g], st + 16384 + row * 128 + (byte ^ ((row & 7) << 4)));      \
        }                                                                          \
    };                                                                             \
    for (int ch = 0; ch < NCHG; ch++) {                                            \
        asm volatile("cp.async.wait_group 1;");                                    \
        __syncthreads();                                                           \
        if (ch + 2 < NCHG) issue(ch + 2);                                          \
        uint32_t st = sb + (ch % GSTAGES) * STG_BYTES;                             \
        load_frags(st, 0, afr[0], bfr[0]);                                         \
        _Pragma("unroll")                                                          \
        for (int kk = 0; kk < 4; kk++) {                                           \
            const int cur = kk & 1;                                                \
            if (kk < 3) load_frags(st, kk + 1, afr[cur ^ 1], bfr[cur ^ 1]);        \
            _Pragma("unroll")                                                      \
            for (int mi = 0; mi < 2; mi++)                                         \
                _Pragma("unroll")                                                  \
                for (int ni = 0; ni < 8; ni++) {                                   \
                    int g = ni >> 1, h = ni & 1;                                   \
                    mma16816h(acc[mi][ni], afr[cur][mi],                           \
                              bfr[cur][g][h], bfr[cur][g][h + 2]);                 \
                }                                                                  \
        }                                                                          \
    }

// ---------------- QKV GEMM with fused operand epilogue (pure fp16) -------------
__global__ __launch_bounds__(256, 2) void gemm_qkv_kernel(
    const __half* __restrict__ A, const __half* __restrict__ B,
    const float* __restrict__ bias)
{
    extern __shared__ char sm[];
    const uint32_t sb = s2u(sm);
    const int tid = threadIdx.x;
    const int wid = tid >> 5, lane = tid & 31;
    const size_t bm = (size_t)blockIdx.y * 128;
    const size_t bn = (size_t)blockIdx.x * 128;
    const int wm = wid & 3, wn = wid >> 2;

    GEMM_MAINLOOP(A, B)

    // ---- fused epilogue (writes fp16 attention operands, all hi-only) ----
    const int r0 = wm * 32 + (lane >> 2);
    const int c0 = wn * 64 + (lane & 3) * 2;
    const int sec = (int)(bn >> 11);            // 0=Q 1=K 2=V
    const int hh  = ((int)bn & 2047) >> 7;
    const int b_  = (int)(bm >> 11);
    const int s_base = (int)bm & 2047;
    const size_t bh = (size_t)b_ * NH + hh;
    const float qscale = 0.08838834764831845f;

    if (sec < 2) {
        __half* dst = (sec == 0) ? g_qs : g_ks;
        const float sc = (sec == 0) ? qscale : 1.f;
#pragma unroll
        for (int mi = 0; mi < 2; mi++)
#pragma unroll
            for (int ni = 0; ni < 8; ni++) {
                int d = c0 + ni * 8;
                float2 bv = *(const float2*)(bias + bn + d);
                unsigned short h0 = __half_as_ushort(__float2half((acc[mi][ni][0] + bv.x) * sc));
                unsigned short h1 = __half_as_ushort(__float2half((acc[mi][ni][1] + bv.y) * sc));
                unsigned short h2 = __half_as_ushort(__float2half((acc[mi][ni][2] + bv.x) * sc));
                unsigned short h3 = __half_as_ushort(__float2half((acc[mi][ni][3] + bv.y) * sc));
                int ra = s_base + r0 + mi * 16;
                __half* pa = dst + (bh * SEQ + ra) * 128 + d;
                *(ushort2*)pa             = make_ushort2(h0,h1);
                *(ushort2*)(pa + 8 * 128) = make_ushort2(h2,h3);
            }
    } else {
        // V: transpose through smem -> g_vt[bh][d][s] (hi only)
        __syncthreads();
        float* smT = (float*)sm;                 // [128 cols][129]
#pragma unroll
        for (int mi = 0; mi < 2; mi++)
#pragma unroll
            for (int ni = 0; ni < 8; ni++) {
                int d = c0 + ni * 8;
                float2 bv = *(const float2*)(bias + bn + d);
                int ra = r0 + mi * 16;
                smT[d * 129 + ra]           = acc[mi][ni][0] + bv.x;
                smT[(d + 1) * 129 + ra]     = acc[mi][ni][1] + bv.y;
                smT[d * 129 + ra + 8]       = acc[mi][ni][2] + bv.x;
                smT[(d + 1) * 129 + ra + 8] = acc[mi][ni][3] + bv.y;
            }
        __syncthreads();
        const int d = tid >> 1;
        const int sOff = (tid & 1) * 64;
        __half* ph = g_vt + (bh * 128 + d) * SEQ + s_base + sOff;
#pragma unroll
        for (int i = 0; i < 16; i++) {
            int s = i * 4;
            ushort4 o = make_ushort4(
                __half_as_ushort(__float2half(smT[d * 129 + sOff + s + 0])),
                __half_as_ushort(__float2half(smT[d * 129 + sOff + s + 1])),
                __half_as_ushort(__float2half(smT[d * 129 + sOff + s + 2])),
                __half_as_ushort(__float2half(smT[d * 129 + sOff + s + 3])));
            *(ushort4*)(ph + s) = o;
        }
    }
}

// ---------------- dense GEMM (pure fp16, fp32 out) ----------------
__global__ __launch_bounds__(256, 2) void gemm_dense_kernel(
    const __half* __restrict__ A, const __half* __restrict__ B,
    const float* __restrict__ bias, float* __restrict__ C, int Ncols)
{
    extern __shared__ char sm[];
    const uint32_t sb = s2u(sm);
    const int tid = threadIdx.x;
    const int wid = tid >> 5, lane = tid & 31;
    const size_t bm = (size_t)blockIdx.y * 128;
    const size_t bn = (size_t)blockIdx.x * 128;
    const int wm = wid & 3, wn = wid >> 2;

    GEMM_MAINLOOP(A, B)

    const int r0 = wm * 32 + (lane >> 2);
    const int c0 = wn * 64 + (lane & 3) * 2;
#pragma unroll
    for (int mi = 0; mi < 2; mi++)
#pragma unroll
        for (int ni = 0; ni < 8; ni++) {
            size_t col = bn + c0 + ni * 8;
            float2 bv = *(const float2*)(bias + col);
            float* p0 = C + (bm + r0 + mi * 16) * (size_t)Ncols + col;
            float* p1 = p0 + 8 * (size_t)Ncols;
            *(float2*)p0 = make_float2(acc[mi][ni][0] + bv.x, acc[mi][ni][1] + bv.y);
            *(float2*)p1 = make_float2(acc[mi][ni][2] + bv.x, acc[mi][ni][3] + bv.y);
        }
}

// ---------------- fp16 HMMA causal flash attention (1-term QK and PV) ----------
// grid (16, NH, BATCH) qb reversed; 256 threads = 8 warps x m16 rows; 3 KV stages.
__global__ __launch_bounds__(256, 1) void attn_hmma_kernel()
{
    extern __shared__ char smc[];
    const uint32_t sb = s2u(smc);
    const int tid = threadIdx.x, w = tid >> 5, lane = tid & 31;
    const int qb = 15 - blockIdx.x, h = blockIdx.y, b = blockIdx.z;
    const int bh = b * NH + h;
    const int nkb = (qb + 1) * 2;
    const int lm_row = lane & 15;
    const int lm_hi  = (lane >> 4) << 4;

    // Q tile: 128 rows x 256B
    {
        const __half* Qg = g_qs + ((size_t)bh * SEQ + qb * 128) * 128;
#pragma unroll
        for (int i = 0; i < 8; i++) {
            int u = i * 256 + tid;
            int r = u >> 4, c = u & 15;
            cp16(sb + r * 256 + ((c * 16) ^ ((r & 7) << 4)), Qg + (size_t)r * 128 + c * 8);
        }
    }
    auto issue_kv = [&](int kb) {
        uint32_t kst = sb + 32768 + (kb % 3) * KV_STG;
        // K: 64 rows x 256B
#pragma unroll
        for (int i = 0; i < 4; i++) {
            int u = i * 256 + tid;
            int r = u >> 4, c = u & 15;
            cp16(kst + r * 256 + ((c * 16) ^ ((r & 7) << 4)),
                 g_ks + ((size_t)bh * SEQ + kb * 64 + r) * 128 + c * 8);
        }
        // V^T: 128 rows x 128B
#pragma unroll
        for (int i = 0; i < 4; i++) {
            int u = i * 256 + tid;
            int r = u >> 3, c = u & 7;
            cp16(kst + 16384 + r * 128 + ((c * 16) ^ ((r & 7) << 4)),
                 g_vt + ((size_t)bh * 128 + r) * SEQ + kb * 64 + c * 8);
        }
        asm volatile("cp.async.commit_group;");
    };
    issue_kv(0);
    if (nkb > 1) issue_kv(1);

    float oacc[16][4];
#pragma unroll
    for (int g = 0; g < 16; g++)
#pragma unroll
        for (int e = 0; e < 4; e++) oacc[g][e] = 0.f;
    float m0 = -1e30f, m1 = -1e30f, lp0 = 0.f, lp1 = 0.f;

    const int row0 = qb * 128 + w * 16 + (lane >> 2);
    const int wrow_max = qb * 128 + w * 16 + 15;

    for (int kb = 0; kb < nkb; kb++) {
        if (kb + 1 < nkb) asm volatile("cp.async.wait_group 1;");
        else              asm volatile("cp.async.wait_group 0;");
        __syncthreads();
        if (kb + 2 < nkb) issue_kv(kb + 2);

        const bool active = (kb * 64) <= wrow_max;
        if (active) {
            const uint32_t kst = sb + 32768 + (kb % 3) * KV_STG;
            const uint32_t vst = kst + 16384;

            // ---- S = Q * K^T (1-term fp16) ----
            float sacc[8][4];
#pragma unroll
            for (int j = 0; j < 8; j++)
#pragma unroll
                for (int e = 0; e < 4; e++) sacc[j][e] = 0.f;

#pragma unroll
            for (int kk = 0; kk < 8; kk++) {
                const int qrow = w * 16 + lm_row;
                uint32_t qa = sb + qrow * 256 +
                              ((uint32_t)(kk * 32 + lm_hi) ^ ((qrow & 7) << 4));
                uint32_t ah[4];
                ldsm4(ah, qa);
#pragma unroll
                for (int g = 0; g < 4; g++) {
                    const int krow = g * 16 + lm_row;
                    uint32_t ka = kst + krow * 256 +
                                  ((uint32_t)(kk * 32 + lm_hi) ^ ((krow & 7) << 4));
                    uint32_t bhh[4];
                    ldsm4(bhh, ka);
                    mma16816h(sacc[2*g],   ah, bhh[0], bhh[2]);
                    mma16816h(sacc[2*g+1], ah, bhh[1], bhh[3]);
                }
            }

            // ---- mask + online softmax ----
            float mx0 = -1e30f, mx1 = -1e30f;
#pragma unroll
            for (int j = 0; j < 8; j++) {
                int colb = kb * 64 + j * 8 + (lane & 3) * 2;
                if (colb     > row0)     sacc[j][0] = -1e30f;
                if (colb + 1 > row0)     sacc[j][1] = -1e30f;
                if (colb     > row0 + 8) sacc[j][2] = -1e30f;
                if (colb + 1 > row0 + 8) sacc[j][3] = -1e30f;
                mx0 = fmaxf(mx0, fmaxf(sacc[j][0], sacc[j][1]));
                mx1 = fmaxf(mx1, fmaxf(sacc[j][2], sacc[j][3]));
            }
            mx0 = fmaxf(mx0, __shfl_xor_sync(0xffffffffu, mx0, 1));
            mx0 = fmaxf(mx0, __shfl_xor_sync(0xffffffffu, mx0, 2));
            mx1 = fmaxf(mx1, __shfl_xor_sync(0xffffffffu, mx1, 1));
            mx1 = fmaxf(mx1, __shfl_xor_sync(0xffffffffu, mx1, 2));
            float mn0 = fmaxf(m0, mx0), mn1 = fmaxf(m1, mx1);
            float al0 = __expf(m0 - mn0), al1 = __expf(m1 - mn1);
            m0 = mn0; m1 = mn1;
            float s0 = 0.f, s1 = 0.f;
#pragma unroll
            for (int j = 0; j < 8; j++) {
                sacc[j][0] = __expf(sacc[j][0] - mn0); s0 += sacc[j][0];
                sacc[j][1] = __expf(sacc[j][1] - mn0); s0 += sacc[j][1];
                sacc[j][2] = __expf(sacc[j][2] - mn1); s1 += sacc[j][2];
                sacc[j][3] = __expf(sacc[j][3] - mn1); s1 += sacc[j][3];
            }
            lp0 = lp0 * al0 + s0;
            lp1 = lp1 * al1 + s1;
#pragma unroll
            for (int g = 0; g < 16; g++) {
                oacc[g][0] *= al0; oacc[g][1] *= al0;
                oacc[g][2] *= al1; oacc[g][3] *= al1;
            }

            // ---- O += P * V (1-term fp16) ----
#pragma unroll
            for (int t = 0; t < 4; t++) {
                const int f0 = 2 * t, f1 = 2 * t + 1;
                uint32_t aPh[4];
                aPh[0] = pkhf(sacc[f0][0], sacc[f0][1]);
                aPh[1] = pkhf(sacc[f0][2], sacc[f0][3]);
                aPh[2] = pkhf(sacc[f1][0], sacc[f1][1]);
                aPh[3] = pkhf(sacc[f1][2], sacc[f1][3]);
#pragma unroll
                for (int g = 0; g < 8; g++) {
                    const int vrow = g * 16 + lm_row;
                    uint32_t va = vst + vrow * 128 +
                                  ((uint32_t)(t * 32 + lm_hi) ^ ((vrow & 7) << 4));
                    uint32_t bhh[4];
                    ldsm4(bhh, va);
                    mma16816h(oacc[2*g],   aPh, bhh[0], bhh[2]);
                    mma16816h(oacc[2*g+1], aPh, bhh[1], bhh[3]);
                }
            }
        }
    }

    lp0 += __shfl_xor_sync(0xffffffffu, lp0, 1);
    lp0 += __shfl_xor_sync(0xffffffffu, lp0, 2);
    lp1 += __shfl_xor_sync(0xffffffffu, lp1, 1);
    lp1 += __shfl_xor_sync(0xffffffffu, lp1, 2);
    const float inv0 = 1.f / lp0, inv1 = 1.f / lp1;

    // ---- write O as plain fp16 (g_attnc, dense GEMM input) ----
    const size_t row = (size_t)b * SEQ + qb * 128 + w * 16 + (lane >> 2);
    const int colb = h * 128 + (lane & 3) * 2;
#pragma unroll
    for (int g = 0; g < 16; g++) {
        int col = colb + g * 8;
        unsigned short h0 = __half_as_ushort(__float2half(oacc[g][0] * inv0));
        unsigned short h1 = __half_as_ushort(__float2half(oacc[g][1] * inv0));
        unsigned short h2 = __half_as_ushort(__float2half(oacc[g][2] * inv1));
        unsigned short h3 = __half_as_ushort(__float2half(oacc[g][3] * inv1));
        __half* pa = g_attnc + row * KH + col;
        *(ushort2*)pa            = make_ushort2(h0,h1);
        *(ushort2*)(pa + 8 * KH) = make_ushort2(h2,h3);
    }
}

// ---------------- launch ----------------
extern "C" void kernel_launch(void* const* d_in, const int* in_sizes, int n_in,
                              void* d_out, int out_size)
{
    (void)in_sizes; (void)n_in; (void)out_size;
    const float* x       = (const float*)d_in[0];
    const float* w_qkv   = (const float*)d_in[1];
    const float* b_qkv   = (const float*)d_in[2];
    const float* w_dense = (const float*)d_in[3];
    const float* b_dense = (const float*)d_in[4];
    float* out = (float*)d_out;

    __half *xc, *wqkvc, *wdc, *attnc;
    cudaGetSymbolAddress((void**)&xc, g_xc);
    cudaGetSymbolAddress((void**)&wqkvc, g_wqkvc);
    cudaGetSymbolAddress((void**)&wdc, g_wdc);
    cudaGetSymbolAddress((void**)&attnc, g_attnc);

    cudaFuncSetAttribute(gemm_qkv_kernel,
                         cudaFuncAttributeMaxDynamicSharedMemorySize, GEMM_SMEM);
    cudaFuncSetAttribute(gemm_dense_kernel,
                         cudaFuncAttributeMaxDynamicSharedMemorySize, GEMM_SMEM);
    cudaFuncSetAttribute(attn_hmma_kernel,
                         cudaFuncAttributeMaxDynamicSharedMemorySize, ATTN_SMEM);

    // fused converts (fp32 -> fp16)
    {
        size_t total4 = N4_X + N4_WQ + N4_WD;
        cvt_all_kernel<<<(unsigned)((total4 + 255) / 256), 256>>>(x, w_qkv, w_dense);
    }

    // 1) QKV GEMM with fused operand-prep epilogue (pure fp16)
    gemm_qkv_kernel<<<dim3(HID3 / 128, MROWS / 128), 256, GEMM_SMEM>>>(
        xc, wqkvc, b_qkv);

    // 2) fp16 HMMA flash attention (1-term QK and PV)
    attn_hmma_kernel<<<dim3(16, NH, BATCH), 256, ATTN_SMEM>>>();

    // 3) out = attn @ Wdense^T + b (pure fp16)
    gemm_dense_kernel<<<dim3(HID / 128, MROWS / 128), 256, GEMM_SMEM>>>(
        attnc, wdc, b_dense, out, HID);
}